// round 1
// baseline (speedup 1.0000x reference)
#include <cuda_runtime.h>
#include <math.h>
#include <stdint.h>
#include <stddef.h>

#define L 2048
#define C 512
#define CZ 16
#define H 16
#define D 32
#define EPS 1e-5f

// ---------------- scratch (static device globals; no allocation) ----------------
__device__ float g_ss[4 * C];                    // [ss1(1024) | ss2(1024)]
__device__ float g_h[L * C];
__device__ float g_q[L * C];
__device__ float g_k[L * C];
__device__ float g_v[L * C];
__device__ float g_scores[(size_t)H * L * L];    // 268 MB
__device__ float g_ao[L * C];
__device__ float g_x1[L * C];
__device__ float g_h2[L * C];
__device__ float g_ff[L * 4 * C];                // 16 MB

// ---------------- adaLN condition projections: ss = cond @ W + b ----------------
__global__ void ss_kernel(const float* __restrict__ cond,
                          const float* __restrict__ w1, const float* __restrict__ b1,
                          const float* __restrict__ w2, const float* __restrict__ b2) {
    int j = blockIdx.x * blockDim.x + threadIdx.x;   // 0..2047
    if (j >= 4 * C) return;
    const float* w = (j < 2 * C) ? w1 : w2;
    const float* b = (j < 2 * C) ? b1 : b2;
    int jj = j & (2 * C - 1);
    float s = 0.f;
    for (int c = 0; c < C; c++) s += cond[c] * w[c * (2 * C) + jj];
    g_ss[j] = s + b[jj];
}

// ---------------- adaLN: out = LN(x)*(1+scale) + shift ----------------
__global__ __launch_bounds__(256) void adaln_kernel(const float* __restrict__ x,
                                                    const float* __restrict__ g,
                                                    const float* __restrict__ b,
                                                    int ss_off, float* __restrict__ out) {
    int row = blockIdx.x;
    int t = threadIdx.x;                              // 256 threads, 2 elems each
    const float* xr = x + (size_t)row * C;
    float v0 = xr[t], v1 = xr[t + 256];
    __shared__ float red[256];
    red[t] = v0 + v1;
    __syncthreads();
    for (int s = 128; s > 0; s >>= 1) { if (t < s) red[t] += red[t + s]; __syncthreads(); }
    float mu = red[0] * (1.0f / C);
    __syncthreads();
    float d0 = v0 - mu, d1 = v1 - mu;
    red[t] = d0 * d0 + d1 * d1;
    __syncthreads();
    for (int s = 128; s > 0; s >>= 1) { if (t < s) red[t] += red[t + s]; __syncthreads(); }
    float rs = rsqrtf(red[0] * (1.0f / C) + EPS);
    const float* scale = g_ss + ss_off;
    const float* shift = g_ss + ss_off + C;
    int c0 = t, c1 = t + 256;
    out[(size_t)row * C + c0] = (d0 * rs * g[c0] + b[c0]) * (1.f + scale[c0]) + shift[c0];
    out[(size_t)row * C + c1] = (d1 * rs * g[c1] + b[c1]) * (1.f + scale[c1]) + shift[c1];
}

// ---------------- generic fp32 SGEMM: 128x128x8, 8x8 per thread ----------------
// Cm[M,N] = A[M,K] @ B[K,N]  (+bias[n]) (+gelu) (+res[m,n])
template <int HAS_BIAS, int HAS_RES, int ACT_GELU>
__global__ __launch_bounds__(256) void sgemm_kernel(const float* __restrict__ A,
                                                    const float* __restrict__ B,
                                                    const float* __restrict__ bias,
                                                    const float* __restrict__ res,
                                                    float* __restrict__ Cm,
                                                    int M, int N, int K) {
    const int BK = 8;
    __shared__ float As[BK][128];
    __shared__ float Bs[BK][128];
    int bx = blockIdx.x, by = blockIdx.y;
    int t = threadIdx.x;
    int tx = t & 15, ty = t >> 4;
    float acc[8][8];
    #pragma unroll
    for (int i = 0; i < 8; i++)
        #pragma unroll
        for (int j = 0; j < 8; j++) acc[i][j] = 0.f;

    int arow = t >> 1, acol4 = (t & 1) * 4;
    int brow = t >> 5, bcol4 = (t & 31) * 4;
    const float* Ab = A + (size_t)(by * 128) * K;
    const float* Bb = B + bx * 128;

    for (int k0 = 0; k0 < K; k0 += BK) {
        float4 a4 = *(const float4*)(Ab + (size_t)arow * K + k0 + acol4);
        As[acol4 + 0][arow] = a4.x;
        As[acol4 + 1][arow] = a4.y;
        As[acol4 + 2][arow] = a4.z;
        As[acol4 + 3][arow] = a4.w;
        float4 b4 = *(const float4*)(Bb + (size_t)(k0 + brow) * N + bcol4);
        *(float4*)&Bs[brow][bcol4] = b4;
        __syncthreads();
        #pragma unroll
        for (int k = 0; k < BK; k++) {
            float ar[8], br[8];
            #pragma unroll
            for (int i = 0; i < 8; i++) ar[i] = As[k][ty * 8 + i];
            #pragma unroll
            for (int j = 0; j < 8; j++) br[j] = Bs[k][tx * 8 + j];
            #pragma unroll
            for (int i = 0; i < 8; i++)
                #pragma unroll
                for (int j = 0; j < 8; j++) acc[i][j] += ar[i] * br[j];
        }
        __syncthreads();
    }

    #pragma unroll
    for (int i = 0; i < 8; i++) {
        int m = by * 128 + ty * 8 + i;
        #pragma unroll
        for (int j = 0; j < 8; j++) {
            int n = bx * 128 + tx * 8 + j;
            float v = acc[i][j];
            if (HAS_BIAS) v += bias[n];
            if (ACT_GELU) v = 0.5f * v * (1.0f + erff(v * 0.70710678118654752f));
            if (HAS_RES) v += res[(size_t)m * N + n];
            Cm[(size_t)m * N + n] = v;
        }
    }
}

// ---------------- scores: S[h,i,j] = q[i,h,:].k[j,h,:] / sqrt(D) ----------------
// block tile: 128 (i) x 64 (j), full K=32
__global__ __launch_bounds__(256) void scores_kernel(const float* __restrict__ q,
                                                     const float* __restrict__ k) {
    int h = blockIdx.z;
    int i0 = blockIdx.y * 128, j0 = blockIdx.x * 64;
    __shared__ float qs[128][33];
    __shared__ float ks[64][33];
    int t = threadIdx.x;
    for (int idx = t; idx < 128 * 32; idx += 256) {
        int r = idx >> 5, c = idx & 31;
        qs[r][c] = q[(size_t)(i0 + r) * C + h * D + c];
    }
    for (int idx = t; idx < 64 * 32; idx += 256) {
        int r = idx >> 5, c = idx & 31;
        ks[r][c] = k[(size_t)(j0 + r) * C + h * D + c];
    }
    __syncthreads();
    int tx = t & 15, ty = t >> 4;        // ty: 16 groups of 8 i-rows, tx: 16 groups of 4 j-cols
    float acc[8][4];
    #pragma unroll
    for (int i = 0; i < 8; i++)
        #pragma unroll
        for (int j = 0; j < 4; j++) acc[i][j] = 0.f;
    #pragma unroll 4
    for (int kk = 0; kk < 32; kk++) {
        float a[8], b[4];
        #pragma unroll
        for (int i = 0; i < 8; i++) a[i] = qs[ty * 8 + i][kk];
        #pragma unroll
        for (int j = 0; j < 4; j++) b[j] = ks[tx * 4 + j][kk];
        #pragma unroll
        for (int i = 0; i < 8; i++)
            #pragma unroll
            for (int j = 0; j < 4; j++) acc[i][j] += a[i] * b[j];
    }
    const float sc = 0.17677669529663687f;   // 1/sqrt(32)
    float* S = g_scores + (size_t)h * L * L;
    #pragma unroll
    for (int i = 0; i < 8; i++)
        #pragma unroll
        for (int j = 0; j < 4; j++)
            S[(size_t)(i0 + ty * 8 + i) * L + j0 + tx * 4 + j] = acc[i][j] * sc;
}

// ---------------- pair bias RMW: S[h,i,j] += pair[i,j,:] . Wpb[:,h] ----------------
__global__ __launch_bounds__(256) void bias_kernel(const float* __restrict__ pair,
                                                   const float* __restrict__ Wpb) {
    __shared__ float w[CZ][H];
    int t = threadIdx.x;
    w[t >> 4][t & 15] = Wpb[t & 255];
    __syncthreads();
    size_t ij = (size_t)blockIdx.x * 256 + t;   // flattened i*L + j
    float p[CZ];
    const float* pp = pair + ij * CZ;
    #pragma unroll
    for (int z = 0; z < CZ; z++) p[z] = pp[z];
    #pragma unroll
    for (int h = 0; h < H; h++) {
        float b = 0.f;
        #pragma unroll
        for (int z = 0; z < CZ; z++) b += p[z] * w[z][h];
        g_scores[(size_t)h * L * L + ij] += b;
    }
}

// ---------------- row softmax over j (values kept in registers) ----------------
__global__ __launch_bounds__(256) void softmax_kernel() {
    float* S = g_scores + (size_t)blockIdx.x * L;
    int t = threadIdx.x;
    float v[8];
    float mx = -1e30f;
    #pragma unroll
    for (int e = 0; e < 8; e++) { v[e] = S[t + e * 256]; mx = fmaxf(mx, v[e]); }
    __shared__ float red[256];
    red[t] = mx;
    __syncthreads();
    for (int s = 128; s > 0; s >>= 1) { if (t < s) red[t] = fmaxf(red[t], red[t + s]); __syncthreads(); }
    mx = red[0];
    __syncthreads();
    float sum = 0.f;
    #pragma unroll
    for (int e = 0; e < 8; e++) { v[e] = __expf(v[e] - mx); sum += v[e]; }
    red[t] = sum;
    __syncthreads();
    for (int s = 128; s > 0; s >>= 1) { if (t < s) red[t] += red[t + s]; __syncthreads(); }
    float inv = 1.0f / red[0];
    #pragma unroll
    for (int e = 0; e < 8; e++) S[t + e * 256] = v[e] * inv;
}

// ---------------- AV: out[i, h*D+d] = sum_j attn[h,i,j] * v[j, h*D+d] ----------------
__global__ __launch_bounds__(256) void av_kernel(const float* __restrict__ v) {
    int h = blockIdx.y;
    int i0 = blockIdx.x * 64;
    int t = threadIdx.x;
    int d = t & 31, wr = t >> 5;     // 8 warps, each owns rows {wr, wr+8, ..., wr+56}
    __shared__ float As[64][65];
    __shared__ float Vs[64][33];
    float acc[8];
    #pragma unroll
    for (int r = 0; r < 8; r++) acc[r] = 0.f;
    const float* Sb = g_scores + (size_t)h * L * L;
    for (int j0 = 0; j0 < L; j0 += 64) {
        for (int idx = t; idx < 64 * 64; idx += 256) {
            int r = idx >> 6, c2 = idx & 63;
            As[r][c2] = Sb[(size_t)(i0 + r) * L + j0 + c2];
        }
        for (int idx = t; idx < 64 * 32; idx += 256) {
            int r = idx >> 5, c2 = idx & 31;
            Vs[r][c2] = v[(size_t)(j0 + r) * C + h * D + c2];
        }
        __syncthreads();
        #pragma unroll 4
        for (int jj = 0; jj < 64; jj++) {
            float vv = Vs[jj][d];
            #pragma unroll
            for (int r8 = 0; r8 < 8; r8++) acc[r8] += As[wr + r8 * 8][jj] * vv;
        }
        __syncthreads();
    }
    #pragma unroll
    for (int r8 = 0; r8 < 8; r8++)
        g_ao[(size_t)(i0 + wr + r8 * 8) * C + h * D + d] = acc[r8];
}

// ---------------- launch ----------------
extern "C" void kernel_launch(void* const* d_in, const int* in_sizes, int n_in,
                              void* d_out, int out_size) {
    const float* x        = (const float*)d_in[0];
    const float* pair     = (const float*)d_in[1];
    const float* time_cond= (const float*)d_in[2];
    const float* ln1_g    = (const float*)d_in[3];
    const float* ln1_b    = (const float*)d_in[4];
    const float* ada1_w   = (const float*)d_in[5];
    const float* ada1_b   = (const float*)d_in[6];
    const float* Wq       = (const float*)d_in[7];
    const float* Wk       = (const float*)d_in[8];
    const float* Wv       = (const float*)d_in[9];
    const float* Wpb      = (const float*)d_in[10];
    const float* Wo       = (const float*)d_in[11];
    const float* bo       = (const float*)d_in[12];
    const float* ln2_g    = (const float*)d_in[13];
    const float* ln2_b    = (const float*)d_in[14];
    const float* ada2_w   = (const float*)d_in[15];
    const float* ada2_b   = (const float*)d_in[16];
    const float* W1       = (const float*)d_in[17];
    const float* b1       = (const float*)d_in[18];
    const float* W2       = (const float*)d_in[19];
    const float* b2       = (const float*)d_in[20];
    float* out = (float*)d_out;

    float *p_h, *p_q, *p_k, *p_v, *p_ao, *p_x1, *p_h2, *p_ff;
    cudaGetSymbolAddress((void**)&p_h,  g_h);
    cudaGetSymbolAddress((void**)&p_q,  g_q);
    cudaGetSymbolAddress((void**)&p_k,  g_k);
    cudaGetSymbolAddress((void**)&p_v,  g_v);
    cudaGetSymbolAddress((void**)&p_ao, g_ao);
    cudaGetSymbolAddress((void**)&p_x1, g_x1);
    cudaGetSymbolAddress((void**)&p_h2, g_h2);
    cudaGetSymbolAddress((void**)&p_ff, g_ff);

    // 1. condition projections (both adaLN blocks)
    ss_kernel<<<8, 256>>>(time_cond, ada1_w, ada1_b, ada2_w, ada2_b);

    // 2. adaLN 1
    adaln_kernel<<<L, 256>>>(x, ln1_g, ln1_b, 0, p_h);

    // 3. QKV projections
    sgemm_kernel<0, 0, 0><<<dim3(4, 16), 256>>>(p_h, Wq, nullptr, nullptr, p_q, L, C, C);
    sgemm_kernel<0, 0, 0><<<dim3(4, 16), 256>>>(p_h, Wk, nullptr, nullptr, p_k, L, C, C);
    sgemm_kernel<0, 0, 0><<<dim3(4, 16), 256>>>(p_h, Wv, nullptr, nullptr, p_v, L, C, C);

    // 4. per-head scores
    scores_kernel<<<dim3(L / 64, L / 128, H), 256>>>(p_q, p_k);

    // 5. pair bias RMW
    bias_kernel<<<(L * L) / 256, 256>>>(pair, Wpb);

    // 6. softmax over j
    softmax_kernel<<<H * L, 256>>>();

    // 7. attn @ V
    av_kernel<<<dim3(L / 64, H), 256>>>(p_v);

    // 8. output projection + residual: x1 = x + ao@Wo + bo
    sgemm_kernel<1, 1, 0><<<dim3(4, 16), 256>>>(p_ao, Wo, bo, x, p_x1, L, C, C);

    // 9. adaLN 2
    adaln_kernel<<<L, 256>>>(p_x1, ln2_g, ln2_b, 2 * C, p_h2);

    // 10. FFN up + exact GELU
    sgemm_kernel<1, 0, 1><<<dim3(16, 16), 256>>>(p_h2, W1, b1, nullptr, p_ff, L, 4 * C, C);

    // 11. FFN down + residual -> final output
    sgemm_kernel<1, 1, 0><<<dim3(4, 16), 256>>>(p_ff, W2, b2, p_x1, out, L, C, 4 * C);
}

// round 2
// speedup vs baseline: 1.5838x; 1.5838x over previous
#include <cuda_runtime.h>
#include <math.h>
#include <stdint.h>
#include <stddef.h>

#define L 2048
#define C 512
#define CZ 16
#define H 16
#define D 32
#define EPS 1e-5f

// ---------------- scratch (static device globals; no allocation) ----------------
__device__ float g_ss[4 * C];                    // [ss1(1024) | ss2(1024)]
__device__ float g_h[L * C];
__device__ float g_q[L * C];
__device__ float g_k[L * C];
__device__ float g_v[L * C];
__device__ float g_bias[(size_t)H * L * L];      // 268 MB precomputed pair bias
__device__ float g_ao[L * C];
__device__ float g_x1[L * C];
__device__ float g_h2[L * C];
__device__ float g_ff[L * 4 * C];                // 16 MB

// ---------------- adaLN condition projections: ss = cond @ W + b ----------------
__global__ void ss_kernel(const float* __restrict__ cond,
                          const float* __restrict__ w1, const float* __restrict__ b1,
                          const float* __restrict__ w2, const float* __restrict__ b2) {
    int j = blockIdx.x * blockDim.x + threadIdx.x;   // 0..2047
    if (j >= 4 * C) return;
    const float* w = (j < 2 * C) ? w1 : w2;
    const float* b = (j < 2 * C) ? b1 : b2;
    int jj = j & (2 * C - 1);
    float s = 0.f;
    for (int c = 0; c < C; c++) s += cond[c] * w[c * (2 * C) + jj];
    g_ss[j] = s + b[jj];
}

// ---------------- adaLN: out = LN(x)*(1+scale) + shift ----------------
__global__ __launch_bounds__(256) void adaln_kernel(const float* __restrict__ x,
                                                    const float* __restrict__ g,
                                                    const float* __restrict__ b,
                                                    int ss_off, float* __restrict__ out) {
    int row = blockIdx.x;
    int t = threadIdx.x;
    const float* xr = x + (size_t)row * C;
    float v0 = xr[t], v1 = xr[t + 256];
    __shared__ float red[256];
    red[t] = v0 + v1;
    __syncthreads();
    for (int s = 128; s > 0; s >>= 1) { if (t < s) red[t] += red[t + s]; __syncthreads(); }
    float mu = red[0] * (1.0f / C);
    __syncthreads();
    float d0 = v0 - mu, d1 = v1 - mu;
    red[t] = d0 * d0 + d1 * d1;
    __syncthreads();
    for (int s = 128; s > 0; s >>= 1) { if (t < s) red[t] += red[t + s]; __syncthreads(); }
    float rs = rsqrtf(red[0] * (1.0f / C) + EPS);
    const float* scale = g_ss + ss_off;
    const float* shift = g_ss + ss_off + C;
    int c0 = t, c1 = t + 256;
    out[(size_t)row * C + c0] = (d0 * rs * g[c0] + b[c0]) * (1.f + scale[c0]) + shift[c0];
    out[(size_t)row * C + c1] = (d1 * rs * g[c1] + b[c1]) * (1.f + scale[c1]) + shift[c1];
}

// ---------------- fp32 SGEMM body: 128x128x8, 8x8 per thread ----------------
template <int HAS_BIAS, int HAS_RES, int ACT_GELU>
__device__ __forceinline__ void sgemm128_body(const float* __restrict__ A,
                                              const float* __restrict__ B,
                                              const float* __restrict__ bias,
                                              const float* __restrict__ res,
                                              float* __restrict__ Cm,
                                              int M, int N, int K, int bx, int by) {
    const int BK = 8;
    __shared__ float As[BK][128];
    __shared__ float Bs[BK][128];
    int t = threadIdx.x;
    int tx = t & 15, ty = t >> 4;
    float acc[8][8];
    #pragma unroll
    for (int i = 0; i < 8; i++)
        #pragma unroll
        for (int j = 0; j < 8; j++) acc[i][j] = 0.f;

    int arow = t >> 1, acol4 = (t & 1) * 4;
    int brow = t >> 5, bcol4 = (t & 31) * 4;
    const float* Ab = A + (size_t)(by * 128) * K;
    const float* Bb = B + bx * 128;

    for (int k0 = 0; k0 < K; k0 += BK) {
        float4 a4 = *(const float4*)(Ab + (size_t)arow * K + k0 + acol4);
        As[acol4 + 0][arow] = a4.x;
        As[acol4 + 1][arow] = a4.y;
        As[acol4 + 2][arow] = a4.z;
        As[acol4 + 3][arow] = a4.w;
        float4 b4 = *(const float4*)(Bb + (size_t)(k0 + brow) * N + bcol4);
        *(float4*)&Bs[brow][bcol4] = b4;
        __syncthreads();
        #pragma unroll
        for (int k = 0; k < BK; k++) {
            float ar[8], br[8];
            #pragma unroll
            for (int i = 0; i < 8; i++) ar[i] = As[k][ty * 8 + i];
            #pragma unroll
            for (int j = 0; j < 8; j++) br[j] = Bs[k][tx * 8 + j];
            #pragma unroll
            for (int i = 0; i < 8; i++)
                #pragma unroll
                for (int j = 0; j < 8; j++) acc[i][j] += ar[i] * br[j];
        }
        __syncthreads();
    }

    #pragma unroll
    for (int i = 0; i < 8; i++) {
        int m = by * 128 + ty * 8 + i;
        #pragma unroll
        for (int j = 0; j < 8; j++) {
            int n = bx * 128 + tx * 8 + j;
            float v = acc[i][j];
            if (HAS_BIAS) v += bias[n];
            if (ACT_GELU) v = 0.5f * v * (1.0f + erff(v * 0.70710678118654752f));
            if (HAS_RES) v += res[(size_t)m * N + n];
            Cm[(size_t)m * N + n] = v;
        }
    }
}

template <int HAS_BIAS, int HAS_RES, int ACT_GELU>
__global__ __launch_bounds__(256) void sgemm_kernel(const float* __restrict__ A,
                                                    const float* __restrict__ B,
                                                    const float* __restrict__ bias,
                                                    const float* __restrict__ res,
                                                    float* __restrict__ Cm,
                                                    int M, int N, int K) {
    sgemm128_body<HAS_BIAS, HAS_RES, ACT_GELU>(A, B, bias, res, Cm, M, N, K,
                                               blockIdx.x, blockIdx.y);
}

// QKV merged: grid.x = 12 (4 col-tiles x 3 weights), grid.y = 16 row-tiles
__global__ __launch_bounds__(256) void qkv_kernel(const float* __restrict__ hbuf,
                                                  const float* __restrict__ Wq,
                                                  const float* __restrict__ Wk,
                                                  const float* __restrict__ Wv,
                                                  float* __restrict__ q,
                                                  float* __restrict__ k,
                                                  float* __restrict__ v) {
    int sel = blockIdx.x >> 2;
    int bxx = blockIdx.x & 3;
    const float* B = (sel == 0) ? Wq : (sel == 1) ? Wk : Wv;
    float* O = (sel == 0) ? q : (sel == 1) ? k : v;
    sgemm128_body<0, 0, 0>(hbuf, B, nullptr, nullptr, O, L, C, C, bxx, blockIdx.y);
}

// ---------------- fp32 SGEMM 128x64x16, 8x4 per thread (bias+res always) ----------------
__global__ __launch_bounds__(256) void sgemm_n64(const float* __restrict__ A,
                                                 const float* __restrict__ B,
                                                 const float* __restrict__ bias,
                                                 const float* __restrict__ res,
                                                 float* __restrict__ Cm,
                                                 int M, int N, int K) {
    const int BK = 16;
    __shared__ float As[BK][128];
    __shared__ float Bs[BK][64];
    int bx = blockIdx.x, by = blockIdx.y;
    int t = threadIdx.x;
    int tx = t & 15, ty = t >> 4;
    float acc[8][4];
    #pragma unroll
    for (int i = 0; i < 8; i++)
        #pragma unroll
        for (int j = 0; j < 4; j++) acc[i][j] = 0.f;

    int arow = t >> 1, acol8 = (t & 1) * 8;       // 2 threads per A row, 8 k each
    int brow = t >> 4, bcol4 = (t & 15) * 4;      // 16 B rows, 16 threads x float4
    const float* Ab = A + (size_t)(by * 128) * K;
    const float* Bb = B + bx * 64;

    for (int k0 = 0; k0 < K; k0 += BK) {
        #pragma unroll
        for (int h4 = 0; h4 < 2; h4++) {
            float4 a4 = *(const float4*)(Ab + (size_t)arow * K + k0 + acol8 + h4 * 4);
            As[acol8 + h4 * 4 + 0][arow] = a4.x;
            As[acol8 + h4 * 4 + 1][arow] = a4.y;
            As[acol8 + h4 * 4 + 2][arow] = a4.z;
            As[acol8 + h4 * 4 + 3][arow] = a4.w;
        }
        float4 b4 = *(const float4*)(Bb + (size_t)(k0 + brow) * N + bcol4);
        *(float4*)&Bs[brow][bcol4] = b4;
        __syncthreads();
        #pragma unroll
        for (int k = 0; k < BK; k++) {
            float ar[8], br[4];
            #pragma unroll
            for (int i = 0; i < 8; i++) ar[i] = As[k][ty * 8 + i];
            #pragma unroll
            for (int j = 0; j < 4; j++) br[j] = Bs[k][tx * 4 + j];
            #pragma unroll
            for (int i = 0; i < 8; i++)
                #pragma unroll
                for (int j = 0; j < 4; j++) acc[i][j] += ar[i] * br[j];
        }
        __syncthreads();
    }

    #pragma unroll
    for (int i = 0; i < 8; i++) {
        int m = by * 128 + ty * 8 + i;
        #pragma unroll
        for (int j = 0; j < 4; j++) {
            int n = bx * 64 + tx * 4 + j;
            Cm[(size_t)m * N + n] = acc[i][j] + bias[n] + res[(size_t)m * N + n];
        }
    }
}

// ---------------- pair bias precompute: bias[h,i,j] = pair[i,j,:] . Wpb[:,h] ----------------
__global__ __launch_bounds__(256) void bias_kernel(const float* __restrict__ pair,
                                                   const float* __restrict__ Wpb) {
    __shared__ float w[CZ][H];
    int t = threadIdx.x;
    w[t >> 4][t & 15] = Wpb[t & 255];
    __syncthreads();
    size_t ij = (size_t)blockIdx.x * 256 + t;   // flattened i*L + j
    float p[CZ];
    const float* pp = pair + ij * CZ;
    #pragma unroll
    for (int z = 0; z < CZ; z++) p[z] = pp[z];
    #pragma unroll
    for (int h = 0; h < H; h++) {
        float b = 0.f;
        #pragma unroll
        for (int z = 0; z < CZ; z++) b += p[z] * w[z][h];
        g_bias[(size_t)h * L * L + ij] = b;      // write-only, no RMW
    }
}

// ---------------- fused flash attention: scores + bias + softmax + AV ----------------
// block: one head h (blockIdx.y), 64 query rows (blockIdx.x). 256 threads.
__global__ __launch_bounds__(256) void flash_kernel(const float* __restrict__ q,
                                                    const float* __restrict__ k,
                                                    const float* __restrict__ v,
                                                    float* __restrict__ out) {
    int h = blockIdx.y;
    int i0 = blockIdx.x * 64;
    int t = threadIdx.x;
    int tx = t & 15, ty = t >> 4;     // score mapping: 4 rows (ty) x 4 cols (tx)
    int d = t & 31, wr = t >> 5;      // AV mapping: warp wr owns rows wr*8..wr*8+7, lane d

    __shared__ float Qs[64][33];
    __shared__ float Ks[64][33];
    __shared__ float Vs[64][33];
    __shared__ float Ps[64][65];
    __shared__ float row_scale[64];
    __shared__ float row_l[64];

    // load Q tile once
    for (int idx = t; idx < 64 * 32; idx += 256) {
        int r = idx >> 5, c = idx & 31;
        Qs[r][c] = q[(size_t)(i0 + r) * C + h * D + c];
    }

    float m_st[4], l_st[4];
    #pragma unroll
    for (int i = 0; i < 4; i++) { m_st[i] = -1e30f; l_st[i] = 0.f; }
    float oacc[8];
    #pragma unroll
    for (int r8 = 0; r8 < 8; r8++) oacc[r8] = 0.f;

    const float* Bh = g_bias + (size_t)h * L * L;
    const float sc = 0.17677669529663687f;   // 1/sqrt(32)
    __syncthreads();

    for (int j0 = 0; j0 < L; j0 += 64) {
        // load K,V tiles
        for (int idx = t; idx < 64 * 32; idx += 256) {
            int r = idx >> 5, c = idx & 31;
            Ks[r][c] = k[(size_t)(j0 + r) * C + h * D + c];
            Vs[r][c] = v[(size_t)(j0 + r) * C + h * D + c];
        }
        __syncthreads();

        // --- QK^T 4x4 per thread ---
        float s[4][4];
        #pragma unroll
        for (int i = 0; i < 4; i++)
            #pragma unroll
            for (int j = 0; j < 4; j++) s[i][j] = 0.f;
        #pragma unroll 4
        for (int kk = 0; kk < 32; kk++) {
            float a[4], b[4];
            #pragma unroll
            for (int i = 0; i < 4; i++) a[i] = Qs[ty * 4 + i][kk];
            #pragma unroll
            for (int j = 0; j < 4; j++) b[j] = Ks[tx * 4 + j][kk];
            #pragma unroll
            for (int i = 0; i < 4; i++)
                #pragma unroll
                for (int j = 0; j < 4; j++) s[i][j] += a[i] * b[j];
        }
        // add pair bias (coalesced float4 per row)
        #pragma unroll
        for (int i = 0; i < 4; i++) {
            float4 b4 = *(const float4*)(Bh + (size_t)(i0 + ty * 4 + i) * L + j0 + tx * 4);
            s[i][0] = s[i][0] * sc + b4.x;
            s[i][1] = s[i][1] * sc + b4.y;
            s[i][2] = s[i][2] * sc + b4.z;
            s[i][3] = s[i][3] * sc + b4.w;
        }

        // --- online softmax (reduce across tx = low 4 lane bits) ---
        #pragma unroll
        for (int i = 0; i < 4; i++) {
            float rm = fmaxf(fmaxf(s[i][0], s[i][1]), fmaxf(s[i][2], s[i][3]));
            #pragma unroll
            for (int off = 1; off < 16; off <<= 1)
                rm = fmaxf(rm, __shfl_xor_sync(0xffffffffu, rm, off));
            float m_new = fmaxf(m_st[i], rm);
            float scale = __expf(m_st[i] - m_new);
            float ps = 0.f;
            #pragma unroll
            for (int j = 0; j < 4; j++) {
                float e = __expf(s[i][j] - m_new);
                Ps[ty * 4 + i][tx * 4 + j] = e;
                ps += e;
            }
            #pragma unroll
            for (int off = 1; off < 16; off <<= 1)
                ps += __shfl_xor_sync(0xffffffffu, ps, off);
            l_st[i] = l_st[i] * scale + ps;
            m_st[i] = m_new;
            if (tx == 0) row_scale[ty * 4 + i] = scale;
        }
        __syncthreads();

        // --- AV accumulate with rescale ---
        #pragma unroll
        for (int r8 = 0; r8 < 8; r8++) {
            int row = wr * 8 + r8;
            float a = oacc[r8] * row_scale[row];
            #pragma unroll 8
            for (int jj = 0; jj < 64; jj++)
                a += Ps[row][jj] * Vs[jj][d];
            oacc[r8] = a;
        }
        __syncthreads();
    }

    if (tx == 0) {
        #pragma unroll
        for (int i = 0; i < 4; i++) row_l[ty * 4 + i] = l_st[i];
    }
    __syncthreads();
    #pragma unroll
    for (int r8 = 0; r8 < 8; r8++) {
        int row = wr * 8 + r8;
        out[(size_t)(i0 + row) * C + h * D + d] = oacc[r8] / row_l[row];
    }
}

// ---------------- launch ----------------
extern "C" void kernel_launch(void* const* d_in, const int* in_sizes, int n_in,
                              void* d_out, int out_size) {
    const float* x        = (const float*)d_in[0];
    const float* pair     = (const float*)d_in[1];
    const float* time_cond= (const float*)d_in[2];
    const float* ln1_g    = (const float*)d_in[3];
    const float* ln1_b    = (const float*)d_in[4];
    const float* ada1_w   = (const float*)d_in[5];
    const float* ada1_b   = (const float*)d_in[6];
    const float* Wq       = (const float*)d_in[7];
    const float* Wk       = (const float*)d_in[8];
    const float* Wv       = (const float*)d_in[9];
    const float* Wpb      = (const float*)d_in[10];
    const float* Wo       = (const float*)d_in[11];
    const float* bo       = (const float*)d_in[12];
    const float* ln2_g    = (const float*)d_in[13];
    const float* ln2_b    = (const float*)d_in[14];
    const float* ada2_w   = (const float*)d_in[15];
    const float* ada2_b   = (const float*)d_in[16];
    const float* W1       = (const float*)d_in[17];
    const float* b1       = (const float*)d_in[18];
    const float* W2       = (const float*)d_in[19];
    const float* b2       = (const float*)d_in[20];
    float* out = (float*)d_out;

    float *p_h, *p_q, *p_k, *p_v, *p_ao, *p_x1, *p_h2, *p_ff;
    cudaGetSymbolAddress((void**)&p_h,  g_h);
    cudaGetSymbolAddress((void**)&p_q,  g_q);
    cudaGetSymbolAddress((void**)&p_k,  g_k);
    cudaGetSymbolAddress((void**)&p_v,  g_v);
    cudaGetSymbolAddress((void**)&p_ao, g_ao);
    cudaGetSymbolAddress((void**)&p_x1, g_x1);
    cudaGetSymbolAddress((void**)&p_h2, g_h2);
    cudaGetSymbolAddress((void**)&p_ff, g_ff);

    // 1. condition projections + pair bias precompute (independent of x path)
    ss_kernel<<<8, 256>>>(time_cond, ada1_w, ada1_b, ada2_w, ada2_b);
    bias_kernel<<<(L * L) / 256, 256>>>(pair, Wpb);

    // 2. adaLN 1
    adaln_kernel<<<L, 256>>>(x, ln1_g, ln1_b, 0, p_h);

    // 3. QKV projections (merged: 192 blocks)
    qkv_kernel<<<dim3(12, 16), 256>>>(p_h, Wq, Wk, Wv, p_q, p_k, p_v);

    // 4. fused flash attention
    flash_kernel<<<dim3(L / 64, H), 256>>>(p_q, p_k, p_v, p_ao);

    // 5. output projection + residual: x1 = x + ao@Wo + bo  (128 blocks)
    sgemm_n64<<<dim3(8, 16), 256>>>(p_ao, Wo, bo, x, p_x1, L, C, C);

    // 6. adaLN 2
    adaln_kernel<<<L, 256>>>(p_x1, ln2_g, ln2_b, 2 * C, p_h2);

    // 7. FFN up + exact GELU (256 blocks)
    sgemm_kernel<1, 0, 1><<<dim3(16, 16), 256>>>(p_h2, W1, b1, nullptr, p_ff, L, 4 * C, C);

    // 8. FFN down + residual -> final output (128 blocks)
    sgemm_n64<<<dim3(8, 16), 256>>>(p_ff, W2, b2, p_x1, out, L, C, 4 * C);
}

// round 3
// speedup vs baseline: 3.5433x; 2.2372x over previous
#include <cuda_runtime.h>
#include <cuda_bf16.h>
#include <math.h>
#include <stdint.h>
#include <stddef.h>

#define L 2048
#define C 512
#define CZ 16
#define H 16
#define D 32
#define EPS 1e-5f

// ---------------- scratch (static device globals; no allocation) ----------------
__device__ float g_ss[4 * C];
__device__ float g_h[L * C];
__device__ float g_q[L * C];
__device__ float g_k[L * C];
__device__ float g_v[L * C];
__device__ __nv_bfloat16 g_bias16[(size_t)H * L * L];   // 134 MB pair bias (bf16)
__device__ float g_ao[L * C];
__device__ float g_x1[L * C];
__device__ float g_h2[L * C];
__device__ float g_ff[L * 4 * C];

// ---------------- tf32 mma helpers ----------------
__device__ __forceinline__ uint32_t f2tf(float f) {
    uint32_t u; asm("cvt.rna.tf32.f32 %0, %1;" : "=r"(u) : "f"(f)); return u;
}
__device__ __forceinline__ void mma8(float (&c)[4], const uint32_t (&a)[4],
                                     uint32_t b0, uint32_t b1) {
    asm volatile("mma.sync.aligned.m16n8k8.row.col.f32.tf32.tf32.f32 "
                 "{%0,%1,%2,%3},{%4,%5,%6,%7},{%8,%9},{%0,%1,%2,%3};"
                 : "+f"(c[0]), "+f"(c[1]), "+f"(c[2]), "+f"(c[3])
                 : "r"(a[0]), "r"(a[1]), "r"(a[2]), "r"(a[3]), "r"(b0), "r"(b1));
}

// ---------------- adaLN condition projections ----------------
__global__ void ss_kernel(const float* __restrict__ cond,
                          const float* __restrict__ w1, const float* __restrict__ b1,
                          const float* __restrict__ w2, const float* __restrict__ b2) {
    int j = blockIdx.x * blockDim.x + threadIdx.x;
    if (j >= 4 * C) return;
    const float* w = (j < 2 * C) ? w1 : w2;
    const float* b = (j < 2 * C) ? b1 : b2;
    int jj = j & (2 * C - 1);
    float s = 0.f;
    for (int c = 0; c < C; c++) s += cond[c] * w[c * (2 * C) + jj];
    g_ss[j] = s + b[jj];
}

// ---------------- adaLN ----------------
__global__ __launch_bounds__(256) void adaln_kernel(const float* __restrict__ x,
                                                    const float* __restrict__ g,
                                                    const float* __restrict__ b,
                                                    int ss_off, float* __restrict__ out) {
    int row = blockIdx.x;
    int t = threadIdx.x;
    const float* xr = x + (size_t)row * C;
    float v0 = xr[t], v1 = xr[t + 256];
    __shared__ float red[256];
    red[t] = v0 + v1;
    __syncthreads();
    for (int s = 128; s > 0; s >>= 1) { if (t < s) red[t] += red[t + s]; __syncthreads(); }
    float mu = red[0] * (1.0f / C);
    __syncthreads();
    float d0 = v0 - mu, d1 = v1 - mu;
    red[t] = d0 * d0 + d1 * d1;
    __syncthreads();
    for (int s = 128; s > 0; s >>= 1) { if (t < s) red[t] += red[t + s]; __syncthreads(); }
    float rs = rsqrtf(red[0] * (1.0f / C) + EPS);
    const float* scale = g_ss + ss_off;
    const float* shift = g_ss + ss_off + C;
    int c0 = t, c1 = t + 256;
    out[(size_t)row * C + c0] = (d0 * rs * g[c0] + b[c0]) * (1.f + scale[c0]) + shift[c0];
    out[(size_t)row * C + c1] = (d1 * rs * g[c1] + b[c1]) * (1.f + scale[c1]) + shift[c1];
}

// ---------------- pair bias precompute (bf16 out) ----------------
__global__ __launch_bounds__(256) void bias_kernel(const float* __restrict__ pair,
                                                   const float* __restrict__ Wpb) {
    __shared__ float w[CZ][H];
    int t = threadIdx.x;
    w[t >> 4][t & 15] = Wpb[t & 255];
    __syncthreads();
    size_t ij = (size_t)blockIdx.x * 256 + t;
    float p[CZ];
    const float* pp = pair + ij * CZ;
    #pragma unroll
    for (int z = 0; z < CZ; z++) p[z] = pp[z];
    #pragma unroll
    for (int h = 0; h < H; h++) {
        float b = 0.f;
        #pragma unroll
        for (int z = 0; z < CZ; z++) b += p[z] * w[z][h];
        g_bias16[(size_t)h * L * L + ij] = __float2bfloat16(b);
    }
}

// ---------------- tf32 MMA GEMM body ----------------
// Tile BM=128 x BN=NB*16, BK=16. 256 threads = 8 warps (4 m x 2 n), warp tile 32 x NB*8.
template <int NB, int HAS_BIAS, int HAS_RES, int ACT_GELU>
__device__ __forceinline__ void mma_gemm_body(const float* __restrict__ A,
                                              const float* __restrict__ B,
                                              const float* __restrict__ bias,
                                              const float* __restrict__ res,
                                              float* __restrict__ Cm,
                                              int N, int K, int bx, int by) {
    const int BN = NB * 16;
    __shared__ uint32_t As[16][136];
    __shared__ uint32_t Bs[16][BN + 8];
    int t = threadIdx.x;
    int warp = t >> 5, lane = t & 31;
    int wm = warp >> 1, wn = warp & 1;
    int r = lane >> 2, qd = lane & 3;
    int row0 = by * 128, bn0 = bx * BN;

    float acc[2][NB][4];
    #pragma unroll
    for (int mi = 0; mi < 2; mi++)
        #pragma unroll
        for (int nb = 0; nb < NB; nb++)
            #pragma unroll
            for (int e = 0; e < 4; e++) acc[mi][nb][e] = 0.f;

    int am = t >> 1, akh = (t & 1) * 8;
    const float* Arow = A + (size_t)(row0 + am) * K;

    for (int k0 = 0; k0 < K; k0 += 16) {
        // stage A (transposed to [k][m], tf32-rounded)
        float4 x0 = *(const float4*)(Arow + k0 + akh);
        float4 x1 = *(const float4*)(Arow + k0 + akh + 4);
        As[akh + 0][am] = f2tf(x0.x); As[akh + 1][am] = f2tf(x0.y);
        As[akh + 2][am] = f2tf(x0.z); As[akh + 3][am] = f2tf(x0.w);
        As[akh + 4][am] = f2tf(x1.x); As[akh + 5][am] = f2tf(x1.y);
        As[akh + 6][am] = f2tf(x1.z); As[akh + 7][am] = f2tf(x1.w);
        // stage B ([k][n], tf32-rounded)
        if (NB == 8) {
            int kr = t >> 4, n8 = (t & 15) * 8;
            const float* Bp = B + (size_t)(k0 + kr) * N + bn0 + n8;
            float4 b0 = *(const float4*)(Bp);
            float4 b1 = *(const float4*)(Bp + 4);
            Bs[kr][n8 + 0] = f2tf(b0.x); Bs[kr][n8 + 1] = f2tf(b0.y);
            Bs[kr][n8 + 2] = f2tf(b0.z); Bs[kr][n8 + 3] = f2tf(b0.w);
            Bs[kr][n8 + 4] = f2tf(b1.x); Bs[kr][n8 + 5] = f2tf(b1.y);
            Bs[kr][n8 + 6] = f2tf(b1.z); Bs[kr][n8 + 7] = f2tf(b1.w);
        } else {
            int kr = t >> 4, n4 = (t & 15) * 4;
            const float* Bp = B + (size_t)(k0 + kr) * N + bn0 + n4;
            float4 b0 = *(const float4*)(Bp);
            Bs[kr][n4 + 0] = f2tf(b0.x); Bs[kr][n4 + 1] = f2tf(b0.y);
            Bs[kr][n4 + 2] = f2tf(b0.z); Bs[kr][n4 + 3] = f2tf(b0.w);
        }
        __syncthreads();
        #pragma unroll
        for (int kk = 0; kk < 16; kk += 8) {
            uint32_t a[2][4];
            #pragma unroll
            for (int mi = 0; mi < 2; mi++) {
                int mo = wm * 32 + mi * 16 + r;
                a[mi][0] = As[kk + qd][mo];
                a[mi][1] = As[kk + qd][mo + 8];
                a[mi][2] = As[kk + qd + 4][mo];
                a[mi][3] = As[kk + qd + 4][mo + 8];
            }
            #pragma unroll
            for (int nb = 0; nb < NB; nb++) {
                int nc = wn * NB * 8 + nb * 8 + r;
                uint32_t b0 = Bs[kk + qd][nc];
                uint32_t b1 = Bs[kk + qd + 4][nc];
                mma8(acc[0][nb], a[0], b0, b1);
                mma8(acc[1][nb], a[1], b0, b1);
            }
        }
        __syncthreads();
    }

    #pragma unroll
    for (int mi = 0; mi < 2; mi++) {
        #pragma unroll
        for (int nb = 0; nb < NB; nb++) {
            int m = row0 + wm * 32 + mi * 16 + r;
            int n = bn0 + wn * NB * 8 + nb * 8 + 2 * qd;
            float v0 = acc[mi][nb][0], v1 = acc[mi][nb][1];
            float v2 = acc[mi][nb][2], v3 = acc[mi][nb][3];
            if (HAS_BIAS) {
                float b0 = bias[n], b1 = bias[n + 1];
                v0 += b0; v1 += b1; v2 += b0; v3 += b1;
            }
            if (ACT_GELU) {
                v0 = 0.5f * v0 * (1.0f + erff(v0 * 0.70710678118654752f));
                v1 = 0.5f * v1 * (1.0f + erff(v1 * 0.70710678118654752f));
                v2 = 0.5f * v2 * (1.0f + erff(v2 * 0.70710678118654752f));
                v3 = 0.5f * v3 * (1.0f + erff(v3 * 0.70710678118654752f));
            }
            if (HAS_RES) {
                float2 r0 = *(const float2*)(res + (size_t)m * N + n);
                float2 r1 = *(const float2*)(res + (size_t)(m + 8) * N + n);
                v0 += r0.x; v1 += r0.y; v2 += r1.x; v3 += r1.y;
            }
            float2 o0 = {v0, v1}, o1 = {v2, v3};
            *(float2*)(Cm + (size_t)m * N + n) = o0;
            *(float2*)(Cm + (size_t)(m + 8) * N + n) = o1;
        }
    }
}

__global__ __launch_bounds__(256) void qkv_mma(const float* __restrict__ hbuf,
                                               const float* __restrict__ Wq,
                                               const float* __restrict__ Wk,
                                               const float* __restrict__ Wv,
                                               float* __restrict__ q,
                                               float* __restrict__ k,
                                               float* __restrict__ v) {
    int sel = blockIdx.x >> 2, bxx = blockIdx.x & 3;
    const float* B = (sel == 0) ? Wq : (sel == 1) ? Wk : Wv;
    float* O = (sel == 0) ? q : (sel == 1) ? k : v;
    mma_gemm_body<8, 0, 0, 0>(hbuf, B, nullptr, nullptr, O, C, C, bxx, blockIdx.y);
}

__global__ __launch_bounds__(256) void ffn1_mma(const float* __restrict__ A,
                                                const float* __restrict__ B,
                                                const float* __restrict__ bias,
                                                float* __restrict__ Cm) {
    mma_gemm_body<8, 1, 0, 1>(A, B, bias, nullptr, Cm, 4 * C, C, blockIdx.x, blockIdx.y);
}

__global__ __launch_bounds__(256) void gemm_bias_res_mma(const float* __restrict__ A,
                                                         const float* __restrict__ B,
                                                         const float* __restrict__ bias,
                                                         const float* __restrict__ res,
                                                         float* __restrict__ Cm,
                                                         int N, int K) {
    mma_gemm_body<4, 1, 1, 0>(A, B, bias, res, Cm, N, K, blockIdx.x, blockIdx.y);
}

// ---------------- flash attention with tf32 mma ----------------
// block = (64 q-rows, 1 head), 128 threads = 4 warps, each warp owns 16 q-rows.
__global__ __launch_bounds__(128) void flash_kernel(const float* __restrict__ q,
                                                    const float* __restrict__ k,
                                                    const float* __restrict__ v,
                                                    float* __restrict__ out) {
    int h = blockIdx.y;
    int i0 = blockIdx.x * 64;
    int t = threadIdx.x;
    int w = t >> 5, lane = t & 31;
    int r = lane >> 2, qd = lane & 3;

    __shared__ uint32_t Ks[64][36];          // [j][c], tf32
    __shared__ uint32_t Vs[64][40];          // [j][d], tf32
    __shared__ uint32_t Ps[4][16][68];       // per-warp P [row][j], tf32

    // Q fragments, loaded once (rows i0 + w*16 + r/+8)
    int qrow0 = i0 + w * 16 + r;
    uint32_t qa[4][4];
    #pragma unroll
    for (int ks = 0; ks < 4; ks++) {
        qa[ks][0] = f2tf(q[(size_t)qrow0 * C + h * D + ks * 8 + qd]);
        qa[ks][1] = f2tf(q[(size_t)(qrow0 + 8) * C + h * D + ks * 8 + qd]);
        qa[ks][2] = f2tf(q[(size_t)qrow0 * C + h * D + ks * 8 + qd + 4]);
        qa[ks][3] = f2tf(q[(size_t)(qrow0 + 8) * C + h * D + ks * 8 + qd + 4]);
    }

    float m0 = -1e30f, m1 = -1e30f, l0 = 0.f, l1 = 0.f;
    float o[4][4];
    #pragma unroll
    for (int nb = 0; nb < 4; nb++)
        #pragma unroll
        for (int e = 0; e < 4; e++) o[nb][e] = 0.f;

    const __nv_bfloat16* Bh = g_bias16 + (size_t)h * L * L;
    const float sc = 0.17677669529663687f;   // 1/sqrt(32)

    for (int j0 = 0; j0 < L; j0 += 64) {
        __syncthreads();
        // stage K,V tiles (tf32-rounded)
        #pragma unroll
        for (int i = 0; i < 4; i++) {
            int row = i * 16 + (t >> 3);
            int c4 = (t & 7) * 4;
            float4 kk = *(const float4*)(k + (size_t)(j0 + row) * C + h * D + c4);
            float4 vv = *(const float4*)(v + (size_t)(j0 + row) * C + h * D + c4);
            Ks[row][c4 + 0] = f2tf(kk.x); Ks[row][c4 + 1] = f2tf(kk.y);
            Ks[row][c4 + 2] = f2tf(kk.z); Ks[row][c4 + 3] = f2tf(kk.w);
            Vs[row][c4 + 0] = f2tf(vv.x); Vs[row][c4 + 1] = f2tf(vv.y);
            Vs[row][c4 + 2] = f2tf(vv.z); Vs[row][c4 + 3] = f2tf(vv.w);
        }
        __syncthreads();

        // QK^T: 8 n-blocks of 8 j-cols
        float s[8][4];
        const __nv_bfloat16* br0 = Bh + (size_t)qrow0 * L + j0;
        const __nv_bfloat16* br1 = Bh + (size_t)(qrow0 + 8) * L + j0;
        #pragma unroll
        for (int nb = 0; nb < 8; nb++) {
            s[nb][0] = s[nb][1] = s[nb][2] = s[nb][3] = 0.f;
            #pragma unroll
            for (int ks = 0; ks < 4; ks++) {
                uint32_t b0 = Ks[nb * 8 + r][ks * 8 + qd];
                uint32_t b1 = Ks[nb * 8 + r][ks * 8 + qd + 4];
                mma8(s[nb], qa[ks], b0, b1);
            }
            float2 bb0 = __bfloat1622float2(*(const __nv_bfloat162*)(br0 + nb * 8 + 2 * qd));
            float2 bb1 = __bfloat1622float2(*(const __nv_bfloat162*)(br1 + nb * 8 + 2 * qd));
            s[nb][0] = s[nb][0] * sc + bb0.x;
            s[nb][1] = s[nb][1] * sc + bb0.y;
            s[nb][2] = s[nb][2] * sc + bb1.x;
            s[nb][3] = s[nb][3] * sc + bb1.y;
        }

        // online softmax (rows r and r+8; reduce across quad lanes)
        float mx0 = -1e30f, mx1 = -1e30f;
        #pragma unroll
        for (int nb = 0; nb < 8; nb++) {
            mx0 = fmaxf(mx0, fmaxf(s[nb][0], s[nb][1]));
            mx1 = fmaxf(mx1, fmaxf(s[nb][2], s[nb][3]));
        }
        mx0 = fmaxf(mx0, __shfl_xor_sync(0xffffffffu, mx0, 1));
        mx0 = fmaxf(mx0, __shfl_xor_sync(0xffffffffu, mx0, 2));
        mx1 = fmaxf(mx1, __shfl_xor_sync(0xffffffffu, mx1, 1));
        mx1 = fmaxf(mx1, __shfl_xor_sync(0xffffffffu, mx1, 2));
        float mn0 = fmaxf(m0, mx0), mn1 = fmaxf(m1, mx1);
        float esc0 = __expf(m0 - mn0), esc1 = __expf(m1 - mn1);
        m0 = mn0; m1 = mn1;

        float sum0 = 0.f, sum1 = 0.f;
        #pragma unroll
        for (int nb = 0; nb < 8; nb++) {
            float p0 = __expf(s[nb][0] - mn0);
            float p1 = __expf(s[nb][1] - mn0);
            float p2 = __expf(s[nb][2] - mn1);
            float p3 = __expf(s[nb][3] - mn1);
            sum0 += p0 + p1; sum1 += p2 + p3;
            Ps[w][r][nb * 8 + 2 * qd] = f2tf(p0);
            Ps[w][r][nb * 8 + 2 * qd + 1] = f2tf(p1);
            Ps[w][r + 8][nb * 8 + 2 * qd] = f2tf(p2);
            Ps[w][r + 8][nb * 8 + 2 * qd + 1] = f2tf(p3);
        }
        sum0 += __shfl_xor_sync(0xffffffffu, sum0, 1);
        sum0 += __shfl_xor_sync(0xffffffffu, sum0, 2);
        sum1 += __shfl_xor_sync(0xffffffffu, sum1, 1);
        sum1 += __shfl_xor_sync(0xffffffffu, sum1, 2);
        l0 = l0 * esc0 + sum0;
        l1 = l1 * esc1 + sum1;

        // rescale O
        #pragma unroll
        for (int nb = 0; nb < 4; nb++) {
            o[nb][0] *= esc0; o[nb][1] *= esc0;
            o[nb][2] *= esc1; o[nb][3] *= esc1;
        }
        __syncwarp();

        // P @ V : k-dim = 64 j (8 steps), n = 32 d (4 blocks)
        #pragma unroll
        for (int ks = 0; ks < 8; ks++) {
            uint32_t pa[4];
            pa[0] = Ps[w][r][ks * 8 + qd];
            pa[1] = Ps[w][r + 8][ks * 8 + qd];
            pa[2] = Ps[w][r][ks * 8 + qd + 4];
            pa[3] = Ps[w][r + 8][ks * 8 + qd + 4];
            #pragma unroll
            for (int nbd = 0; nbd < 4; nbd++) {
                uint32_t vb0 = Vs[ks * 8 + qd][nbd * 8 + r];
                uint32_t vb1 = Vs[ks * 8 + qd + 4][nbd * 8 + r];
                mma8(o[nbd], pa, vb0, vb1);
            }
        }
        __syncwarp();
    }

    float il0 = 1.0f / l0, il1 = 1.0f / l1;
    #pragma unroll
    for (int nbd = 0; nbd < 4; nbd++) {
        float2 w0 = {o[nbd][0] * il0, o[nbd][1] * il0};
        float2 w1 = {o[nbd][2] * il1, o[nbd][3] * il1};
        *(float2*)(out + (size_t)qrow0 * C + h * D + nbd * 8 + 2 * qd) = w0;
        *(float2*)(out + (size_t)(qrow0 + 8) * C + h * D + nbd * 8 + 2 * qd) = w1;
    }
}

// ---------------- launch ----------------
extern "C" void kernel_launch(void* const* d_in, const int* in_sizes, int n_in,
                              void* d_out, int out_size) {
    const float* x        = (const float*)d_in[0];
    const float* pair     = (const float*)d_in[1];
    const float* time_cond= (const float*)d_in[2];
    const float* ln1_g    = (const float*)d_in[3];
    const float* ln1_b    = (const float*)d_in[4];
    const float* ada1_w   = (const float*)d_in[5];
    const float* ada1_b   = (const float*)d_in[6];
    const float* Wq       = (const float*)d_in[7];
    const float* Wk       = (const float*)d_in[8];
    const float* Wv       = (const float*)d_in[9];
    const float* Wpb      = (const float*)d_in[10];
    const float* Wo       = (const float*)d_in[11];
    const float* bo       = (const float*)d_in[12];
    const float* ln2_g    = (const float*)d_in[13];
    const float* ln2_b    = (const float*)d_in[14];
    const float* ada2_w   = (const float*)d_in[15];
    const float* ada2_b   = (const float*)d_in[16];
    const float* W1       = (const float*)d_in[17];
    const float* b1       = (const float*)d_in[18];
    const float* W2       = (const float*)d_in[19];
    const float* b2       = (const float*)d_in[20];
    float* out = (float*)d_out;

    float *p_h, *p_q, *p_k, *p_v, *p_ao, *p_x1, *p_h2, *p_ff;
    cudaGetSymbolAddress((void**)&p_h,  g_h);
    cudaGetSymbolAddress((void**)&p_q,  g_q);
    cudaGetSymbolAddress((void**)&p_k,  g_k);
    cudaGetSymbolAddress((void**)&p_v,  g_v);
    cudaGetSymbolAddress((void**)&p_ao, g_ao);
    cudaGetSymbolAddress((void**)&p_x1, g_x1);
    cudaGetSymbolAddress((void**)&p_h2, g_h2);
    cudaGetSymbolAddress((void**)&p_ff, g_ff);

    // independent precomputes
    ss_kernel<<<8, 256>>>(time_cond, ada1_w, ada1_b, ada2_w, ada2_b);
    bias_kernel<<<(L * L) / 256, 256>>>(pair, Wpb);

    // adaLN 1
    adaln_kernel<<<L, 256>>>(x, ln1_g, ln1_b, 0, p_h);

    // QKV (tf32 mma, merged)
    qkv_mma<<<dim3(12, 16), 256>>>(p_h, Wq, Wk, Wv, p_q, p_k, p_v);

    // fused flash attention (tf32 mma)
    flash_kernel<<<dim3(L / 64, H), 128>>>(p_q, p_k, p_v, p_ao);

    // output projection + residual
    gemm_bias_res_mma<<<dim3(8, 16), 256>>>(p_ao, Wo, bo, x, p_x1, C, C);

    // adaLN 2
    adaln_kernel<<<L, 256>>>(p_x1, ln2_g, ln2_b, 2 * C, p_h2);

    // FFN up + exact GELU
    ffn1_mma<<<dim3(16, 16), 256>>>(p_h2, W1, b1, p_ff);

    // FFN down + residual -> out
    gemm_bias_res_mma<<<dim3(8, 16), 256>>>(p_ff, W2, b2, p_x1, out, C, 4 * C);
}

// round 4
// speedup vs baseline: 3.6125x; 1.0195x over previous
#include <cuda_runtime.h>
#include <cuda_bf16.h>
#include <math.h>
#include <stdint.h>
#include <stddef.h>

#define L 2048
#define C 512
#define CZ 16
#define H 16
#define D 32
#define EPS 1e-5f

// ---------------- scratch (static device globals; no allocation) ----------------
__device__ float g_ss[4 * C];
__device__ float g_h[L * C];
__device__ float g_q[L * C];      // tf32-pre-rounded
__device__ float g_k[L * C];      // tf32-pre-rounded
__device__ float g_v[L * C];      // tf32-pre-rounded
__device__ __nv_bfloat16 g_bias16[(size_t)H * L * L];   // 134 MB pair bias (bf16)
__device__ float g_ao[L * C];
__device__ float g_x1[L * C];
__device__ float g_h2[L * C];
__device__ float g_ff[L * 4 * C];

// ---------------- tf32 mma helpers ----------------
__device__ __forceinline__ uint32_t f2tf(float f) {
    uint32_t u; asm("cvt.rna.tf32.f32 %0, %1;" : "=r"(u) : "f"(f)); return u;
}
__device__ __forceinline__ void mma8(float (&c)[4], const uint32_t (&a)[4],
                                     uint32_t b0, uint32_t b1) {
    asm volatile("mma.sync.aligned.m16n8k8.row.col.f32.tf32.tf32.f32 "
                 "{%0,%1,%2,%3},{%4,%5,%6,%7},{%8,%9},{%0,%1,%2,%3};"
                 : "+f"(c[0]), "+f"(c[1]), "+f"(c[2]), "+f"(c[3])
                 : "r"(a[0]), "r"(a[1]), "r"(a[2]), "r"(a[3]), "r"(b0), "r"(b1));
}

// ---------------- adaLN condition projections ----------------
__global__ void ss_kernel(const float* __restrict__ cond,
                          const float* __restrict__ w1, const float* __restrict__ b1,
                          const float* __restrict__ w2, const float* __restrict__ b2) {
    int j = blockIdx.x * blockDim.x + threadIdx.x;
    if (j >= 4 * C) return;
    const float* w = (j < 2 * C) ? w1 : w2;
    const float* b = (j < 2 * C) ? b1 : b2;
    int jj = j & (2 * C - 1);
    float s = 0.f;
    for (int c = 0; c < C; c++) s += cond[c] * w[c * (2 * C) + jj];
    g_ss[j] = s + b[jj];
}

// ---------------- adaLN ----------------
__global__ __launch_bounds__(256) void adaln_kernel(const float* __restrict__ x,
                                                    const float* __restrict__ g,
                                                    const float* __restrict__ b,
                                                    int ss_off, float* __restrict__ out) {
    int row = blockIdx.x;
    int t = threadIdx.x;
    const float* xr = x + (size_t)row * C;
    float v0 = xr[t], v1 = xr[t + 256];
    __shared__ float red[256];
    red[t] = v0 + v1;
    __syncthreads();
    for (int s = 128; s > 0; s >>= 1) { if (t < s) red[t] += red[t + s]; __syncthreads(); }
    float mu = red[0] * (1.0f / C);
    __syncthreads();
    float d0 = v0 - mu, d1 = v1 - mu;
    red[t] = d0 * d0 + d1 * d1;
    __syncthreads();
    for (int s = 128; s > 0; s >>= 1) { if (t < s) red[t] += red[t + s]; __syncthreads(); }
    float rs = rsqrtf(red[0] * (1.0f / C) + EPS);
    const float* scale = g_ss + ss_off;
    const float* shift = g_ss + ss_off + C;
    int c0 = t, c1 = t + 256;
    out[(size_t)row * C + c0] = (d0 * rs * g[c0] + b[c0]) * (1.f + scale[c0]) + shift[c0];
    out[(size_t)row * C + c1] = (d1 * rs * g[c1] + b[c1]) * (1.f + scale[c1]) + shift[c1];
}

// ---------------- pair bias precompute (bf16 out) ----------------
__global__ __launch_bounds__(256) void bias_kernel(const float* __restrict__ pair,
                                                   const float* __restrict__ Wpb) {
    __shared__ float w[CZ][H];
    int t = threadIdx.x;
    w[t >> 4][t & 15] = Wpb[t & 255];
    __syncthreads();
    size_t ij = (size_t)blockIdx.x * 256 + t;
    float p[CZ];
    const float* pp = pair + ij * CZ;
    #pragma unroll
    for (int z = 0; z < CZ; z++) p[z] = pp[z];
    #pragma unroll
    for (int h = 0; h < H; h++) {
        float b = 0.f;
        #pragma unroll
        for (int z = 0; z < CZ; z++) b += p[z] * w[z][h];
        g_bias16[(size_t)h * L * L + ij] = __float2bfloat16(b);
    }
}

// ---------------- tf32 MMA GEMM body (register-prefetch double buffered) ----------------
// Tile BM=128 x BN=NB*16, BK=16. 256 threads = 8 warps (4 m x 2 n), warp tile 32 x NB*8.
// RND_OUT: tf32-round outputs before store (for q/k/v feeding flash).
template <int NB, int HAS_BIAS, int HAS_RES, int ACT_GELU, int RND_OUT>
__device__ __forceinline__ void mma_gemm_body(const float* __restrict__ A,
                                              const float* __restrict__ B,
                                              const float* __restrict__ bias,
                                              const float* __restrict__ res,
                                              float* __restrict__ Cm,
                                              int N, int K, int bx, int by) {
    const int BN = NB * 16;
    __shared__ uint32_t As[16][136];
    __shared__ uint32_t Bs[16][BN + 8];
    int t = threadIdx.x;
    int warp = t >> 5, lane = t & 31;
    int wm = warp >> 1, wn = warp & 1;
    int r = lane >> 2, qd = lane & 3;
    int row0 = by * 128, bn0 = bx * BN;

    float acc[2][NB][4];
    #pragma unroll
    for (int mi = 0; mi < 2; mi++)
        #pragma unroll
        for (int nb = 0; nb < NB; nb++)
            #pragma unroll
            for (int e = 0; e < 4; e++) acc[mi][nb][e] = 0.f;

    int am = t >> 1, akh = (t & 1) * 8;
    const float* Arow = A + (size_t)(row0 + am) * K;
    int bkr = (NB == 8) ? (t >> 4) : (t >> 4);
    int bnc = (NB == 8) ? (t & 15) * 8 : (t & 15) * 4;

    float4 ra0, ra1, rb0, rb1;

    // prologue: load k-tile 0
    ra0 = *(const float4*)(Arow + akh);
    ra1 = *(const float4*)(Arow + akh + 4);
    {
        const float* Bp = B + (size_t)bkr * N + bn0 + bnc;
        rb0 = *(const float4*)(Bp);
        if (NB == 8) rb1 = *(const float4*)(Bp + 4);
    }

    for (int k0 = 0; k0 < K; k0 += 16) {
        // stage current tile from registers
        As[akh + 0][am] = f2tf(ra0.x); As[akh + 1][am] = f2tf(ra0.y);
        As[akh + 2][am] = f2tf(ra0.z); As[akh + 3][am] = f2tf(ra0.w);
        As[akh + 4][am] = f2tf(ra1.x); As[akh + 5][am] = f2tf(ra1.y);
        As[akh + 6][am] = f2tf(ra1.z); As[akh + 7][am] = f2tf(ra1.w);
        Bs[bkr][bnc + 0] = f2tf(rb0.x); Bs[bkr][bnc + 1] = f2tf(rb0.y);
        Bs[bkr][bnc + 2] = f2tf(rb0.z); Bs[bkr][bnc + 3] = f2tf(rb0.w);
        if (NB == 8) {
            Bs[bkr][bnc + 4] = f2tf(rb1.x); Bs[bkr][bnc + 5] = f2tf(rb1.y);
            Bs[bkr][bnc + 6] = f2tf(rb1.z); Bs[bkr][bnc + 7] = f2tf(rb1.w);
        }
        __syncthreads();

        // prefetch next tile (overlaps with MMA below)
        if (k0 + 16 < K) {
            ra0 = *(const float4*)(Arow + k0 + 16 + akh);
            ra1 = *(const float4*)(Arow + k0 + 16 + akh + 4);
            const float* Bp = B + (size_t)(k0 + 16 + bkr) * N + bn0 + bnc;
            rb0 = *(const float4*)(Bp);
            if (NB == 8) rb1 = *(const float4*)(Bp + 4);
        }

        #pragma unroll
        for (int kk = 0; kk < 16; kk += 8) {
            uint32_t a[2][4];
            #pragma unroll
            for (int mi = 0; mi < 2; mi++) {
                int mo = wm * 32 + mi * 16 + r;
                a[mi][0] = As[kk + qd][mo];
                a[mi][1] = As[kk + qd][mo + 8];
                a[mi][2] = As[kk + qd + 4][mo];
                a[mi][3] = As[kk + qd + 4][mo + 8];
            }
            #pragma unroll
            for (int nb = 0; nb < NB; nb++) {
                int nc = wn * NB * 8 + nb * 8 + r;
                uint32_t b0 = Bs[kk + qd][nc];
                uint32_t b1 = Bs[kk + qd + 4][nc];
                mma8(acc[0][nb], a[0], b0, b1);
                mma8(acc[1][nb], a[1], b0, b1);
            }
        }
        __syncthreads();
    }

    #pragma unroll
    for (int mi = 0; mi < 2; mi++) {
        #pragma unroll
        for (int nb = 0; nb < NB; nb++) {
            int m = row0 + wm * 32 + mi * 16 + r;
            int n = bn0 + wn * NB * 8 + nb * 8 + 2 * qd;
            float v0 = acc[mi][nb][0], v1 = acc[mi][nb][1];
            float v2 = acc[mi][nb][2], v3 = acc[mi][nb][3];
            if (HAS_BIAS) {
                float b0 = bias[n], b1 = bias[n + 1];
                v0 += b0; v1 += b1; v2 += b0; v3 += b1;
            }
            if (ACT_GELU) {
                v0 = 0.5f * v0 * (1.0f + erff(v0 * 0.70710678118654752f));
                v1 = 0.5f * v1 * (1.0f + erff(v1 * 0.70710678118654752f));
                v2 = 0.5f * v2 * (1.0f + erff(v2 * 0.70710678118654752f));
                v3 = 0.5f * v3 * (1.0f + erff(v3 * 0.70710678118654752f));
            }
            if (HAS_RES) {
                float2 r0 = *(const float2*)(res + (size_t)m * N + n);
                float2 r1 = *(const float2*)(res + (size_t)(m + 8) * N + n);
                v0 += r0.x; v1 += r0.y; v2 += r1.x; v3 += r1.y;
            }
            if (RND_OUT) {
                v0 = __uint_as_float(f2tf(v0)); v1 = __uint_as_float(f2tf(v1));
                v2 = __uint_as_float(f2tf(v2)); v3 = __uint_as_float(f2tf(v3));
            }
            float2 o0 = {v0, v1}, o1 = {v2, v3};
            *(float2*)(Cm + (size_t)m * N + n) = o0;
            *(float2*)(Cm + (size_t)(m + 8) * N + n) = o1;
        }
    }
}

__global__ __launch_bounds__(256) void qkv_mma(const float* __restrict__ hbuf,
                                               const float* __restrict__ Wq,
                                               const float* __restrict__ Wk,
                                               const float* __restrict__ Wv,
                                               float* __restrict__ q,
                                               float* __restrict__ k,
                                               float* __restrict__ v) {
    int sel = blockIdx.x >> 2, bxx = blockIdx.x & 3;
    const float* B = (sel == 0) ? Wq : (sel == 1) ? Wk : Wv;
    float* O = (sel == 0) ? q : (sel == 1) ? k : v;
    mma_gemm_body<8, 0, 0, 0, 1>(hbuf, B, nullptr, nullptr, O, C, C, bxx, blockIdx.y);
}

__global__ __launch_bounds__(256) void ffn1_mma(const float* __restrict__ A,
                                                const float* __restrict__ B,
                                                const float* __restrict__ bias,
                                                float* __restrict__ Cm) {
    mma_gemm_body<8, 1, 0, 1, 0>(A, B, bias, nullptr, Cm, 4 * C, C, blockIdx.x, blockIdx.y);
}

__global__ __launch_bounds__(256) void gemm_bias_res_mma(const float* __restrict__ A,
                                                         const float* __restrict__ B,
                                                         const float* __restrict__ bias,
                                                         const float* __restrict__ res,
                                                         float* __restrict__ Cm,
                                                         int N, int K) {
    mma_gemm_body<4, 1, 1, 0, 0>(A, B, bias, res, Cm, N, K, blockIdx.x, blockIdx.y);
}

// ---------------- flash attention with tf32 mma (no conversions in loop) ----------------
// block = (64 q-rows, 1 head), 128 threads = 4 warps, each warp owns 16 q-rows.
// q/k/v are tf32-pre-rounded floats: raw bits feed MMA directly.
__global__ __launch_bounds__(128) void flash_kernel(const float* __restrict__ q,
                                                    const float* __restrict__ k,
                                                    const float* __restrict__ v,
                                                    float* __restrict__ out) {
    int h = blockIdx.y;
    int i0 = blockIdx.x * 64;
    int t = threadIdx.x;
    int w = t >> 5, lane = t & 31;
    int r = lane >> 2, qd = lane & 3;

    __shared__ float Ks[64][36];          // [j][c]
    __shared__ float Vs[64][40];          // [j][d]
    __shared__ float Ps[4][16][68];       // per-warp P [row][j]

    // Q fragments (pre-rounded; raw bits)
    int qrow0 = i0 + w * 16 + r;
    uint32_t qa[4][4];
    #pragma unroll
    for (int ks = 0; ks < 4; ks++) {
        qa[ks][0] = __float_as_uint(q[(size_t)qrow0 * C + h * D + ks * 8 + qd]);
        qa[ks][1] = __float_as_uint(q[(size_t)(qrow0 + 8) * C + h * D + ks * 8 + qd]);
        qa[ks][2] = __float_as_uint(q[(size_t)qrow0 * C + h * D + ks * 8 + qd + 4]);
        qa[ks][3] = __float_as_uint(q[(size_t)(qrow0 + 8) * C + h * D + ks * 8 + qd + 4]);
    }

    float m0 = -1e30f, m1 = -1e30f, l0 = 0.f, l1 = 0.f;
    float o[4][4];
    #pragma unroll
    for (int nb = 0; nb < 4; nb++)
        #pragma unroll
        for (int e = 0; e < 4; e++) o[nb][e] = 0.f;

    const __nv_bfloat16* Bh = g_bias16 + (size_t)h * L * L;
    const float sc = 0.17677669529663687f;   // 1/sqrt(32)

    for (int j0 = 0; j0 < L; j0 += 64) {
        __syncthreads();
        // stage K,V tiles — plain vectorized copies (no cvt)
        #pragma unroll
        for (int i = 0; i < 4; i++) {
            int row = i * 16 + (t >> 3);
            int c4 = (t & 7) * 4;
            *(float4*)&Ks[row][c4] = *(const float4*)(k + (size_t)(j0 + row) * C + h * D + c4);
            *(float4*)&Vs[row][c4] = *(const float4*)(v + (size_t)(j0 + row) * C + h * D + c4);
        }
        __syncthreads();

        // QK^T: 8 n-blocks of 8 j-cols
        float s[8][4];
        const __nv_bfloat16* br0 = Bh + (size_t)qrow0 * L + j0;
        const __nv_bfloat16* br1 = Bh + (size_t)(qrow0 + 8) * L + j0;
        #pragma unroll
        for (int nb = 0; nb < 8; nb++) {
            s[nb][0] = s[nb][1] = s[nb][2] = s[nb][3] = 0.f;
            #pragma unroll
            for (int ks = 0; ks < 4; ks++) {
                uint32_t b0 = __float_as_uint(Ks[nb * 8 + r][ks * 8 + qd]);
                uint32_t b1 = __float_as_uint(Ks[nb * 8 + r][ks * 8 + qd + 4]);
                mma8(s[nb], qa[ks], b0, b1);
            }
            float2 bb0 = __bfloat1622float2(*(const __nv_bfloat162*)(br0 + nb * 8 + 2 * qd));
            float2 bb1 = __bfloat1622float2(*(const __nv_bfloat162*)(br1 + nb * 8 + 2 * qd));
            s[nb][0] = s[nb][0] * sc + bb0.x;
            s[nb][1] = s[nb][1] * sc + bb0.y;
            s[nb][2] = s[nb][2] * sc + bb1.x;
            s[nb][3] = s[nb][3] * sc + bb1.y;
        }

        // online softmax
        float mx0 = -1e30f, mx1 = -1e30f;
        #pragma unroll
        for (int nb = 0; nb < 8; nb++) {
            mx0 = fmaxf(mx0, fmaxf(s[nb][0], s[nb][1]));
            mx1 = fmaxf(mx1, fmaxf(s[nb][2], s[nb][3]));
        }
        mx0 = fmaxf(mx0, __shfl_xor_sync(0xffffffffu, mx0, 1));
        mx0 = fmaxf(mx0, __shfl_xor_sync(0xffffffffu, mx0, 2));
        mx1 = fmaxf(mx1, __shfl_xor_sync(0xffffffffu, mx1, 1));
        mx1 = fmaxf(mx1, __shfl_xor_sync(0xffffffffu, mx1, 2));
        float mn0 = fmaxf(m0, mx0), mn1 = fmaxf(m1, mx1);
        float esc0 = __expf(m0 - mn0), esc1 = __expf(m1 - mn1);
        m0 = mn0; m1 = mn1;

        float sum0 = 0.f, sum1 = 0.f;
        #pragma unroll
        for (int nb = 0; nb < 8; nb++) {
            float p0 = __expf(s[nb][0] - mn0);
            float p1 = __expf(s[nb][1] - mn0);
            float p2 = __expf(s[nb][2] - mn1);
            float p3 = __expf(s[nb][3] - mn1);
            sum0 += p0 + p1; sum1 += p2 + p3;
            Ps[w][r][nb * 8 + 2 * qd] = p0;
            Ps[w][r][nb * 8 + 2 * qd + 1] = p1;
            Ps[w][r + 8][nb * 8 + 2 * qd] = p2;
            Ps[w][r + 8][nb * 8 + 2 * qd + 1] = p3;
        }
        sum0 += __shfl_xor_sync(0xffffffffu, sum0, 1);
        sum0 += __shfl_xor_sync(0xffffffffu, sum0, 2);
        sum1 += __shfl_xor_sync(0xffffffffu, sum1, 1);
        sum1 += __shfl_xor_sync(0xffffffffu, sum1, 2);
        l0 = l0 * esc0 + sum0;
        l1 = l1 * esc1 + sum1;

        #pragma unroll
        for (int nb = 0; nb < 4; nb++) {
            o[nb][0] *= esc0; o[nb][1] *= esc0;
            o[nb][2] *= esc1; o[nb][3] *= esc1;
        }
        __syncwarp();

        // P @ V
        #pragma unroll
        for (int ks = 0; ks < 8; ks++) {
            uint32_t pa[4];
            pa[0] = __float_as_uint(Ps[w][r][ks * 8 + qd]);
            pa[1] = __float_as_uint(Ps[w][r + 8][ks * 8 + qd]);
            pa[2] = __float_as_uint(Ps[w][r][ks * 8 + qd + 4]);
            pa[3] = __float_as_uint(Ps[w][r + 8][ks * 8 + qd + 4]);
            #pragma unroll
            for (int nbd = 0; nbd < 4; nbd++) {
                uint32_t vb0 = __float_as_uint(Vs[ks * 8 + qd][nbd * 8 + r]);
                uint32_t vb1 = __float_as_uint(Vs[ks * 8 + qd + 4][nbd * 8 + r]);
                mma8(o[nbd], pa, vb0, vb1);
            }
        }
        __syncwarp();
    }

    float il0 = 1.0f / l0, il1 = 1.0f / l1;
    #pragma unroll
    for (int nbd = 0; nbd < 4; nbd++) {
        float2 w0 = {o[nbd][0] * il0, o[nbd][1] * il0};
        float2 w1 = {o[nbd][2] * il1, o[nbd][3] * il1};
        *(float2*)(out + (size_t)qrow0 * C + h * D + nbd * 8 + 2 * qd) = w0;
        *(float2*)(out + (size_t)(qrow0 + 8) * C + h * D + nbd * 8 + 2 * qd) = w1;
    }
}

// ---------------- launch ----------------
extern "C" void kernel_launch(void* const* d_in, const int* in_sizes, int n_in,
                              void* d_out, int out_size) {
    const float* x        = (const float*)d_in[0];
    const float* pair     = (const float*)d_in[1];
    const float* time_cond= (const float*)d_in[2];
    const float* ln1_g    = (const float*)d_in[3];
    const float* ln1_b    = (const float*)d_in[4];
    const float* ada1_w   = (const float*)d_in[5];
    const float* ada1_b   = (const float*)d_in[6];
    const float* Wq       = (const float*)d_in[7];
    const float* Wk       = (const float*)d_in[8];
    const float* Wv       = (const float*)d_in[9];
    const float* Wpb      = (const float*)d_in[10];
    const float* Wo       = (const float*)d_in[11];
    const float* bo       = (const float*)d_in[12];
    const float* ln2_g    = (const float*)d_in[13];
    const float* ln2_b    = (const float*)d_in[14];
    const float* ada2_w   = (const float*)d_in[15];
    const float* ada2_b   = (const float*)d_in[16];
    const float* W1       = (const float*)d_in[17];
    const float* b1       = (const float*)d_in[18];
    const float* W2       = (const float*)d_in[19];
    const float* b2       = (const float*)d_in[20];
    float* out = (float*)d_out;

    float *p_h, *p_q, *p_k, *p_v, *p_ao, *p_x1, *p_h2, *p_ff;
    cudaGetSymbolAddress((void**)&p_h,  g_h);
    cudaGetSymbolAddress((void**)&p_q,  g_q);
    cudaGetSymbolAddress((void**)&p_k,  g_k);
    cudaGetSymbolAddress((void**)&p_v,  g_v);
    cudaGetSymbolAddress((void**)&p_ao, g_ao);
    cudaGetSymbolAddress((void**)&p_x1, g_x1);
    cudaGetSymbolAddress((void**)&p_h2, g_h2);
    cudaGetSymbolAddress((void**)&p_ff, g_ff);

    ss_kernel<<<8, 256>>>(time_cond, ada1_w, ada1_b, ada2_w, ada2_b);
    bias_kernel<<<(L * L) / 256, 256>>>(pair, Wpb);

    adaln_kernel<<<L, 256>>>(x, ln1_g, ln1_b, 0, p_h);

    qkv_mma<<<dim3(12, 16), 256>>>(p_h, Wq, Wk, Wv, p_q, p_k, p_v);

    flash_kernel<<<dim3(L / 64, H), 128>>>(p_q, p_k, p_v, p_ao);

    gemm_bias_res_mma<<<dim3(8, 16), 256>>>(p_ao, Wo, bo, x, p_x1, C, C);

    adaln_kernel<<<L, 256>>>(p_x1, ln2_g, ln2_b, 2 * C, p_h2);

    ffn1_mma<<<dim3(16, 16), 256>>>(p_h2, W1, b1, p_ff);

    gemm_bias_res_mma<<<dim3(8, 16), 256>>>(p_ff, W2, b2, p_x1, out, C, 4 * C);
}

// round 5
// speedup vs baseline: 4.3509x; 1.2044x over previous
#include <cuda_runtime.h>
#include <cuda_bf16.h>
#include <math.h>
#include <stdint.h>
#include <stddef.h>

#define L 2048
#define C 512
#define CZ 16
#define H 16
#define D 32
#define EPS 1e-5f

#define SZ_CC (C * C)          // 262144
#define SZ_W1 (C * 4 * C)      // 1048576
#define WR_TOT (4 * SZ_CC + 2 * SZ_W1)   // 3145728 floats

// ---------------- scratch ----------------
__device__ float g_ss[4 * C];
__device__ float g_h[L * C];
__device__ float g_q[L * C];      // tf32-rounded, cols permuted within 8
__device__ float g_k[L * C];      // tf32-rounded, cols permuted within 8
__device__ float g_v[L * C];      // tf32-rounded
__device__ float g_wr[WR_TOT];    // tf32-rounded weights
__device__ __nv_bfloat16 g_bias16[(size_t)H * L * L];
__device__ float g_ao[L * C];
__device__ float g_x1[L * C];
__device__ float g_h2[L * C];
__device__ float g_ff[L * 4 * C];

// ---------------- helpers ----------------
__device__ __forceinline__ uint32_t f2tf(float f) {
    uint32_t u; asm("cvt.rna.tf32.f32 %0, %1;" : "=r"(u) : "f"(f)); return u;
}
__device__ __forceinline__ float rnd_tf(float f) { return __uint_as_float(f2tf(f)); }
__device__ __forceinline__ void mma8(float (&c)[4], const uint32_t (&a)[4],
                                     uint32_t b0, uint32_t b1) {
    asm volatile("mma.sync.aligned.m16n8k8.row.col.f32.tf32.tf32.f32 "
                 "{%0,%1,%2,%3},{%4,%5,%6,%7},{%8,%9},{%0,%1,%2,%3};"
                 : "+f"(c[0]), "+f"(c[1]), "+f"(c[2]), "+f"(c[3])
                 : "r"(a[0]), "r"(a[1]), "r"(a[2]), "r"(a[3]), "r"(b0), "r"(b1));
}
__device__ __forceinline__ uint32_t sptr(const void* p) {
    return (uint32_t)__cvta_generic_to_shared(p);
}
#define CPA16(dst, src) asm volatile("cp.async.cg.shared.global [%0], [%1], 16;" :: "r"(dst), "l"(src))
#define CP_COMMIT() asm volatile("cp.async.commit_group;")
#define CP_WAIT1() asm volatile("cp.async.wait_group 1;")
#define CP_WAIT0() asm volatile("cp.async.wait_group 0;")
// permute col within 8: old o -> (o&3)*2 + (o>>2); maps (qd, qd+4) -> (2qd, 2qd+1)
__device__ __forceinline__ int permn(int n) {
    int o = n & 7; return (n & ~7) | ((o & 3) << 1) | (o >> 2);
}

// ---------------- condition projections ----------------
__global__ void ss_kernel(const float* __restrict__ cond,
                          const float* __restrict__ w1, const float* __restrict__ b1,
                          const float* __restrict__ w2, const float* __restrict__ b2) {
    int j = blockIdx.x * blockDim.x + threadIdx.x;
    if (j >= 4 * C) return;
    const float* w = (j < 2 * C) ? w1 : w2;
    const float* b = (j < 2 * C) ? b1 : b2;
    int jj = j & (2 * C - 1);
    float s = 0.f;
    for (int c = 0; c < C; c++) s += cond[c] * w[c * (2 * C) + jj];
    g_ss[j] = s + b[jj];
}

// ---------------- weight tf32 pre-round ----------------
__global__ __launch_bounds__(256) void wround_kernel(const float* __restrict__ Wq,
                                                     const float* __restrict__ Wk,
                                                     const float* __restrict__ Wv,
                                                     const float* __restrict__ Wo,
                                                     const float* __restrict__ W1,
                                                     const float* __restrict__ W2) {
    size_t i = ((size_t)blockIdx.x * 256 + threadIdx.x) * 4;
    const float* src; size_t off;
    if (i < SZ_CC)                    { src = Wq; off = i; }
    else if (i < 2 * (size_t)SZ_CC)   { src = Wk; off = i - SZ_CC; }
    else if (i < 3 * (size_t)SZ_CC)   { src = Wv; off = i - 2 * SZ_CC; }
    else if (i < 4 * (size_t)SZ_CC)   { src = Wo; off = i - 3 * SZ_CC; }
    else if (i < 4 * (size_t)SZ_CC + SZ_W1) { src = W1; off = i - 4 * SZ_CC; }
    else                              { src = W2; off = i - 4 * SZ_CC - SZ_W1; }
    float4 v = *(const float4*)(src + off);
    float4 o;
    o.x = rnd_tf(v.x); o.y = rnd_tf(v.y); o.z = rnd_tf(v.z); o.w = rnd_tf(v.w);
    *(float4*)(g_wr + i) = o;
}

// ---------------- adaLN ----------------
__global__ __launch_bounds__(256) void adaln_kernel(const float* __restrict__ x,
                                                    const float* __restrict__ g,
                                                    const float* __restrict__ b,
                                                    int ss_off, float* __restrict__ out) {
    int row = blockIdx.x;
    int t = threadIdx.x;
    const float* xr = x + (size_t)row * C;
    float v0 = xr[t], v1 = xr[t + 256];
    __shared__ float red[256];
    red[t] = v0 + v1;
    __syncthreads();
    for (int s = 128; s > 0; s >>= 1) { if (t < s) red[t] += red[t + s]; __syncthreads(); }
    float mu = red[0] * (1.0f / C);
    __syncthreads();
    float d0 = v0 - mu, d1 = v1 - mu;
    red[t] = d0 * d0 + d1 * d1;
    __syncthreads();
    for (int s = 128; s > 0; s >>= 1) { if (t < s) red[t] += red[t + s]; __syncthreads(); }
    float rs = rsqrtf(red[0] * (1.0f / C) + EPS);
    const float* scale = g_ss + ss_off;
    const float* shift = g_ss + ss_off + C;
    int c0 = t, c1 = t + 256;
    float o0 = (d0 * rs * g[c0] + b[c0]) * (1.f + scale[c0]) + shift[c0];
    float o1 = (d1 * rs * g[c1] + b[c1]) * (1.f + scale[c1]) + shift[c1];
    out[(size_t)row * C + c0] = rnd_tf(o0);
    out[(size_t)row * C + c1] = rnd_tf(o1);
}

// ---------------- pair bias precompute (bf16 out) ----------------
__global__ __launch_bounds__(256) void bias_kernel(const float* __restrict__ pair,
                                                   const float* __restrict__ Wpb) {
    __shared__ float w[CZ][H];
    int t = threadIdx.x;
    w[t >> 4][t & 15] = Wpb[t & 255];
    __syncthreads();
    size_t ij = (size_t)blockIdx.x * 256 + t;
    float p[CZ];
    const float* pp = pair + ij * CZ;
    #pragma unroll
    for (int z = 0; z < CZ; z++) p[z] = pp[z];
    #pragma unroll
    for (int h = 0; h < H; h++) {
        float b = 0.f;
        #pragma unroll
        for (int z = 0; z < CZ; z++) b += p[z] * w[z][h];
        g_bias16[(size_t)h * L * L + ij] = __float2bfloat16(b);
    }
}

// ---------------- tf32 MMA GEMM, cp.async 2-stage ----------------
// BM=128, BN=NB*16, BK=16. 256 threads = 8 warps (4m x 2n), warp tile 32 x NB*8.
// A, B pre-rounded tf32 in gmem; no cvt inside.
template <int NB, int HAS_BIAS, int HAS_RES, int ACT_GELU, int RND_OUT>
__device__ __forceinline__ void mma_gemm_body(const float* __restrict__ A,
                                              const float* __restrict__ B,
                                              const float* __restrict__ bias,
                                              const float* __restrict__ res,
                                              float* __restrict__ Cm,
                                              int N, int K, int bx, int by, int permqk) {
    const int BN = NB * 16;
    __shared__ float As[2][128][20];
    __shared__ float Bs[2][16][BN + 8];
    int t = threadIdx.x;
    int warp = t >> 5, lane = t & 31;
    int wm = warp >> 1, wn = warp & 1;
    int r = lane >> 2, qd = lane & 3;
    int row0 = by * 128, bn0 = bx * BN;

    float acc[2][NB][4];
    #pragma unroll
    for (int mi = 0; mi < 2; mi++)
        #pragma unroll
        for (int nb = 0; nb < NB; nb++)
            #pragma unroll
            for (int e = 0; e < 4; e++) acc[mi][nb][e] = 0.f;

    auto loadTiles = [&](int s, int k0) {
        #pragma unroll
        for (int c = 0; c < 2; c++) {
            int ch = t + c * 256;
            int m = ch >> 2, kq = (ch & 3) * 4;
            CPA16(sptr(&As[s][m][kq]), A + (size_t)(row0 + m) * K + k0 + kq);
        }
        if (NB == 8) {
            #pragma unroll
            for (int c = 0; c < 2; c++) {
                int ch = t + c * 256;
                int kk = ch >> 5, n4 = (ch & 31) * 4;
                CPA16(sptr(&Bs[s][kk][n4]), B + (size_t)(k0 + kk) * N + bn0 + n4);
            }
        } else {
            int kk = t >> 4, n4 = (t & 15) * 4;
            CPA16(sptr(&Bs[s][kk][n4]), B + (size_t)(k0 + kk) * N + bn0 + n4);
        }
        CP_COMMIT();
    };

    loadTiles(0, 0);
    int T = K >> 4;
    for (int it = 0; it < T; it++) {
        int s = it & 1;
        if (it + 1 < T) { loadTiles(s ^ 1, (it + 1) << 4); CP_WAIT1(); }
        else            { CP_WAIT0(); }
        __syncthreads();
        #pragma unroll
        for (int kk = 0; kk < 16; kk += 8) {
            uint32_t a[2][4];
            #pragma unroll
            for (int mi = 0; mi < 2; mi++) {
                int mo = wm * 32 + mi * 16 + r;
                a[mi][0] = __float_as_uint(As[s][mo][kk + qd]);
                a[mi][1] = __float_as_uint(As[s][mo + 8][kk + qd]);
                a[mi][2] = __float_as_uint(As[s][mo][kk + qd + 4]);
                a[mi][3] = __float_as_uint(As[s][mo + 8][kk + qd + 4]);
            }
            #pragma unroll
            for (int nb = 0; nb < NB; nb++) {
                int nc = wn * NB * 8 + nb * 8 + r;
                uint32_t b0 = __float_as_uint(Bs[s][kk + qd][nc]);
                uint32_t b1 = __float_as_uint(Bs[s][kk + qd + 4][nc]);
                mma8(acc[0][nb], a[0], b0, b1);
                mma8(acc[1][nb], a[1], b0, b1);
            }
        }
        __syncthreads();
    }

    #pragma unroll
    for (int mi = 0; mi < 2; mi++) {
        #pragma unroll
        for (int nb = 0; nb < NB; nb++) {
            int m = row0 + wm * 32 + mi * 16 + r;
            int n = bn0 + wn * NB * 8 + nb * 8 + 2 * qd;
            float v0 = acc[mi][nb][0], v1 = acc[mi][nb][1];
            float v2 = acc[mi][nb][2], v3 = acc[mi][nb][3];
            if (HAS_BIAS) {
                float b0 = bias[n], b1 = bias[n + 1];
                v0 += b0; v1 += b1; v2 += b0; v3 += b1;
            }
            if (ACT_GELU) {
                v0 = 0.5f * v0 * (1.0f + erff(v0 * 0.70710678118654752f));
                v1 = 0.5f * v1 * (1.0f + erff(v1 * 0.70710678118654752f));
                v2 = 0.5f * v2 * (1.0f + erff(v2 * 0.70710678118654752f));
                v3 = 0.5f * v3 * (1.0f + erff(v3 * 0.70710678118654752f));
            }
            if (HAS_RES) {
                float2 r0 = *(const float2*)(res + (size_t)m * N + n);
                float2 r1 = *(const float2*)(res + (size_t)(m + 8) * N + n);
                v0 += r0.x; v1 += r0.y; v2 += r1.x; v3 += r1.y;
            }
            if (RND_OUT) {
                v0 = rnd_tf(v0); v1 = rnd_tf(v1); v2 = rnd_tf(v2); v3 = rnd_tf(v3);
            }
            if (permqk) {
                int p0 = permn(n), p1 = permn(n + 1);
                Cm[(size_t)m * N + p0] = v0;
                Cm[(size_t)m * N + p1] = v1;
                Cm[(size_t)(m + 8) * N + p0] = v2;
                Cm[(size_t)(m + 8) * N + p1] = v3;
            } else {
                float2 o0 = {v0, v1}, o1 = {v2, v3};
                *(float2*)(Cm + (size_t)m * N + n) = o0;
                *(float2*)(Cm + (size_t)(m + 8) * N + n) = o1;
            }
        }
    }
}

__global__ __launch_bounds__(256) void qkv_mma(const float* __restrict__ hbuf,
                                               float* __restrict__ q,
                                               float* __restrict__ k,
                                               float* __restrict__ v) {
    int sel = blockIdx.x >> 2, bxx = blockIdx.x & 3;
    const float* B = g_wr + (size_t)sel * SZ_CC;
    float* O = (sel == 0) ? q : (sel == 1) ? k : v;
    mma_gemm_body<8, 0, 0, 0, 1>(hbuf, B, nullptr, nullptr, O, C, C, bxx, blockIdx.y,
                                 sel != 2);
}

__global__ __launch_bounds__(256) void ffn1_mma(const float* __restrict__ A,
                                                const float* __restrict__ bias,
                                                float* __restrict__ Cm) {
    mma_gemm_body<8, 1, 0, 1, 1>(A, g_wr + 4 * SZ_CC, bias, nullptr, Cm, 4 * C, C,
                                 blockIdx.x, blockIdx.y, 0);
}

__global__ __launch_bounds__(256) void wo_mma(const float* __restrict__ A,
                                              const float* __restrict__ bias,
                                              const float* __restrict__ res,
                                              float* __restrict__ Cm) {
    mma_gemm_body<4, 1, 1, 0, 0>(A, g_wr + 3 * SZ_CC, bias, res, Cm, C, C,
                                 blockIdx.x, blockIdx.y, 0);
}

__global__ __launch_bounds__(256) void ffn2_mma(const float* __restrict__ A,
                                                const float* __restrict__ bias,
                                                const float* __restrict__ res,
                                                float* __restrict__ Cm) {
    mma_gemm_body<4, 1, 1, 0, 0>(A, g_wr + 4 * SZ_CC + SZ_W1, bias, res, Cm, C, 4 * C,
                                 blockIdx.x, blockIdx.y, 0);
}

// ---------------- flash attention: 128 q-rows, 256 threads, cp.async double buffer ----
// dynamic smem layout (bytes):
//   Ks: [2][64][40] f32      @ 0       size 20480   (q/k cols permuted -> LDS.64 frags)
//   Vs: [2][64][40] f32      @ 20480   size 20480
//   Bb: [2][128][72] bf16    @ 40960   size 36864
//   Ps: [8][16][72] f32      @ 77824   size 36864
#define FSMEM_BYTES 114688
__global__ __launch_bounds__(256, 2) void flash_kernel(const float* __restrict__ q,
                                                       const float* __restrict__ k,
                                                       const float* __restrict__ v,
                                                       float* __restrict__ out) {
    extern __shared__ char fsm[];
    float* Ks = (float*)fsm;
    float* Vs = (float*)(fsm + 20480);
    __nv_bfloat16* Bb = (__nv_bfloat16*)(fsm + 40960);
    float* Ps = (float*)(fsm + 77824);

    int h = blockIdx.y;
    int i0 = blockIdx.x * 128;
    int hD = h * D;
    int t = threadIdx.x;
    int w = t >> 5, lane = t & 31;
    int r = lane >> 2, qd = lane & 3;
    int qrow0 = i0 + w * 16 + r;
    const __nv_bfloat16* Bh = g_bias16 + (size_t)h * L * L;

    auto loadKVB = [&](int s, int j0) {
        #pragma unroll
        for (int c = 0; c < 2; c++) {
            int ch = t + c * 256;
            int rw = ch >> 3, kq = (ch & 7) * 4;
            CPA16(sptr(&Ks[(s * 64 + rw) * 40 + kq]), k + (size_t)(j0 + rw) * C + hD + kq);
            CPA16(sptr(&Vs[(s * 64 + rw) * 40 + kq]), v + (size_t)(j0 + rw) * C + hD + kq);
        }
        #pragma unroll
        for (int c = 0; c < 4; c++) {
            int ch = t + c * 256;
            int rw = ch >> 3, e8 = (ch & 7) * 8;
            CPA16(sptr(&Bb[(s * 128 + rw) * 72 + e8]), Bh + (size_t)(i0 + rw) * L + j0 + e8);
        }
        CP_COMMIT();
    };

    loadKVB(0, 0);

    // Q fragments: permuted cols -> float2 gives (old qd, old qd+4)
    uint32_t qa[4][4];
    #pragma unroll
    for (int ks = 0; ks < 4; ks++) {
        float2 q0 = *(const float2*)(q + (size_t)qrow0 * C + hD + ks * 8 + 2 * qd);
        float2 q1 = *(const float2*)(q + (size_t)(qrow0 + 8) * C + hD + ks * 8 + 2 * qd);
        qa[ks][0] = __float_as_uint(q0.x);
        qa[ks][1] = __float_as_uint(q1.x);
        qa[ks][2] = __float_as_uint(q0.y);
        qa[ks][3] = __float_as_uint(q1.y);
    }

    float m0 = -1e30f, m1 = -1e30f, l0 = 0.f, l1 = 0.f;
    float o[4][4];
    #pragma unroll
    for (int nb = 0; nb < 4; nb++)
        #pragma unroll
        for (int e = 0; e < 4; e++) o[nb][e] = 0.f;

    const float sc = 0.17677669529663687f;   // 1/sqrt(32)
    int lr = w * 16 + r;

    for (int jt = 0; jt < L / 64; jt++) {
        int s = jt & 1;
        if (jt + 1 < L / 64) { loadKVB(s ^ 1, (jt + 1) * 64); CP_WAIT1(); }
        else                 { CP_WAIT0(); }
        __syncthreads();

        // QK^T + bias
        float sreg[8][4];
        #pragma unroll
        for (int nb = 0; nb < 8; nb++) {
            sreg[nb][0] = sreg[nb][1] = sreg[nb][2] = sreg[nb][3] = 0.f;
            #pragma unroll
            for (int ks = 0; ks < 4; ks++) {
                float2 kv = *(const float2*)&Ks[(s * 64 + nb * 8 + r) * 40 + ks * 8 + 2 * qd];
                mma8(sreg[nb], qa[ks], __float_as_uint(kv.x), __float_as_uint(kv.y));
            }
            float2 bb0 = __bfloat1622float2(
                *(const __nv_bfloat162*)&Bb[(s * 128 + lr) * 72 + nb * 8 + 2 * qd]);
            float2 bb1 = __bfloat1622float2(
                *(const __nv_bfloat162*)&Bb[(s * 128 + lr + 8) * 72 + nb * 8 + 2 * qd]);
            sreg[nb][0] = sreg[nb][0] * sc + bb0.x;
            sreg[nb][1] = sreg[nb][1] * sc + bb0.y;
            sreg[nb][2] = sreg[nb][2] * sc + bb1.x;
            sreg[nb][3] = sreg[nb][3] * sc + bb1.y;
        }

        // online softmax
        float mx0 = -1e30f, mx1 = -1e30f;
        #pragma unroll
        for (int nb = 0; nb < 8; nb++) {
            mx0 = fmaxf(mx0, fmaxf(sreg[nb][0], sreg[nb][1]));
            mx1 = fmaxf(mx1, fmaxf(sreg[nb][2], sreg[nb][3]));
        }
        mx0 = fmaxf(mx0, __shfl_xor_sync(0xffffffffu, mx0, 1));
        mx0 = fmaxf(mx0, __shfl_xor_sync(0xffffffffu, mx0, 2));
        mx1 = fmaxf(mx1, __shfl_xor_sync(0xffffffffu, mx1, 1));
        mx1 = fmaxf(mx1, __shfl_xor_sync(0xffffffffu, mx1, 2));
        float mn0 = fmaxf(m0, mx0), mn1 = fmaxf(m1, mx1);
        float esc0 = __expf(m0 - mn0), esc1 = __expf(m1 - mn1);
        m0 = mn0; m1 = mn1;

        float sum0 = 0.f, sum1 = 0.f;
        #pragma unroll
        for (int nb = 0; nb < 8; nb++) {
            float p0 = __expf(sreg[nb][0] - mn0);
            float p1 = __expf(sreg[nb][1] - mn0);
            float p2 = __expf(sreg[nb][2] - mn1);
            float p3 = __expf(sreg[nb][3] - mn1);
            sum0 += p0 + p1; sum1 += p2 + p3;
            float2 w0 = {p0, p1}, w1 = {p2, p3};
            *(float2*)&Ps[(w * 16 + r) * 72 + nb * 8 + 2 * qd] = w0;
            *(float2*)&Ps[(w * 16 + r + 8) * 72 + nb * 8 + 2 * qd] = w1;
        }
        sum0 += __shfl_xor_sync(0xffffffffu, sum0, 1);
        sum0 += __shfl_xor_sync(0xffffffffu, sum0, 2);
        sum1 += __shfl_xor_sync(0xffffffffu, sum1, 1);
        sum1 += __shfl_xor_sync(0xffffffffu, sum1, 2);
        l0 = l0 * esc0 + sum0;
        l1 = l1 * esc1 + sum1;

        #pragma unroll
        for (int nb = 0; nb < 4; nb++) {
            o[nb][0] *= esc0; o[nb][1] *= esc0;
            o[nb][2] *= esc1; o[nb][3] *= esc1;
        }
        __syncwarp();

        // P @ V
        #pragma unroll
        for (int ks = 0; ks < 8; ks++) {
            uint32_t pa[4];
            pa[0] = __float_as_uint(Ps[(w * 16 + r) * 72 + ks * 8 + qd]);
            pa[1] = __float_as_uint(Ps[(w * 16 + r + 8) * 72 + ks * 8 + qd]);
            pa[2] = __float_as_uint(Ps[(w * 16 + r) * 72 + ks * 8 + qd + 4]);
            pa[3] = __float_as_uint(Ps[(w * 16 + r + 8) * 72 + ks * 8 + qd + 4]);
            #pragma unroll
            for (int nbd = 0; nbd < 4; nbd++) {
                uint32_t vb0 = __float_as_uint(Vs[(s * 64 + ks * 8 + qd) * 40 + nbd * 8 + r]);
                uint32_t vb1 = __float_as_uint(Vs[(s * 64 + ks * 8 + qd + 4) * 40 + nbd * 8 + r]);
                mma8(o[nbd], pa, vb0, vb1);
            }
        }
        __syncthreads();
    }

    float il0 = 1.0f / l0, il1 = 1.0f / l1;
    #pragma unroll
    for (int nbd = 0; nbd < 4; nbd++) {
        float2 w0 = {rnd_tf(o[nbd][0] * il0), rnd_tf(o[nbd][1] * il0)};
        float2 w1 = {rnd_tf(o[nbd][2] * il1), rnd_tf(o[nbd][3] * il1)};
        *(float2*)(out + (size_t)qrow0 * C + hD + nbd * 8 + 2 * qd) = w0;
        *(float2*)(out + (size_t)(qrow0 + 8) * C + hD + nbd * 8 + 2 * qd) = w1;
    }
}

// ---------------- launch ----------------
extern "C" void kernel_launch(void* const* d_in, const int* in_sizes, int n_in,
                              void* d_out, int out_size) {
    const float* x        = (const float*)d_in[0];
    const float* pair     = (const float*)d_in[1];
    const float* time_cond= (const float*)d_in[2];
    const float* ln1_g    = (const float*)d_in[3];
    const float* ln1_b    = (const float*)d_in[4];
    const float* ada1_w   = (const float*)d_in[5];
    const float* ada1_b   = (const float*)d_in[6];
    const float* Wq       = (const float*)d_in[7];
    const float* Wk       = (const float*)d_in[8];
    const float* Wv       = (const float*)d_in[9];
    const float* Wpb      = (const float*)d_in[10];
    const float* Wo       = (const float*)d_in[11];
    const float* bo       = (const float*)d_in[12];
    const float* ln2_g    = (const float*)d_in[13];
    const float* ln2_b    = (const float*)d_in[14];
    const float* ada2_w   = (const float*)d_in[15];
    const float* ada2_b   = (const float*)d_in[16];
    const float* W1       = (const float*)d_in[17];
    const float* b1       = (const float*)d_in[18];
    const float* W2       = (const float*)d_in[19];
    const float* b2       = (const float*)d_in[20];
    float* out = (float*)d_out;

    float *p_h, *p_q, *p_k, *p_v, *p_ao, *p_x1, *p_h2, *p_ff;
    cudaGetSymbolAddress((void**)&p_h,  g_h);
    cudaGetSymbolAddress((void**)&p_q,  g_q);
    cudaGetSymbolAddress((void**)&p_k,  g_k);
    cudaGetSymbolAddress((void**)&p_v,  g_v);
    cudaGetSymbolAddress((void**)&p_ao, g_ao);
    cudaGetSymbolAddress((void**)&p_x1, g_x1);
    cudaGetSymbolAddress((void**)&p_h2, g_h2);
    cudaGetSymbolAddress((void**)&p_ff, g_ff);

    static int smem_set = 0;
    if (!smem_set) {
        cudaFuncSetAttribute(flash_kernel,
                             cudaFuncAttributeMaxDynamicSharedMemorySize, FSMEM_BYTES);
        smem_set = 1;
    }

    ss_kernel<<<8, 256>>>(time_cond, ada1_w, ada1_b, ada2_w, ada2_b);
    wround_kernel<<<WR_TOT / 1024, 256>>>(Wq, Wk, Wv, Wo, W1, W2);
    bias_kernel<<<(L * L) / 256, 256>>>(pair, Wpb);

    adaln_kernel<<<L, 256>>>(x, ln1_g, ln1_b, 0, p_h);

    qkv_mma<<<dim3(12, 16), 256>>>(p_h, p_q, p_k, p_v);

    flash_kernel<<<dim3(L / 128, H), 256, FSMEM_BYTES>>>(p_q, p_k, p_v, p_ao);

    wo_mma<<<dim3(8, 16), 256>>>(p_ao, bo, x, p_x1);

    adaln_kernel<<<L, 256>>>(p_x1, ln2_g, ln2_b, 2 * C, p_h2);

    ffn1_mma<<<dim3(16, 16), 256>>>(p_h2, b1, p_ff);

    ffn2_mma<<<dim3(8, 16), 256>>>(p_ff, b2, p_x1, out);
}